// round 7
// baseline (speedup 1.0000x reference)
#include <cuda_runtime.h>
#include <cstdint>

#define T_  4096
#define H_  2048
#define I_  1408
#define E_  16
#define TI_ 2816            // 2*I
#define SLOTS (T_*2)        // 8192 (token, expert) pairs

// ---------------- scratch (device globals: no allocation allowed) -----------
__device__ int    g_topk_ids[SLOTS];
__device__ float  g_topk_w[SLOTS];
__device__ int    g_counts[E_];
__device__ int    g_offsets[E_ + 1];
__device__ int    g_cursor[E_];
__device__ int    g_sorted_tok[SLOTS];
__device__ float  g_sorted_w[SLOTS];
__device__ float  g_hbuf[(size_t)SLOTS * I_];   // 46 MB intermediate (silu(g)*u)

// ---------------- helpers ---------------------------------------------------
__device__ __forceinline__ uint32_t f2tf32(float x) {
    uint32_t r;
    asm("cvt.rna.tf32.f32 %0, %1;" : "=r"(r) : "f"(x));
    return r;
}

__device__ __forceinline__ void mma_tf32(float d[4], const uint32_t a[4], const uint32_t b[2]) {
    asm volatile(
        "mma.sync.aligned.m16n8k8.row.col.f32.tf32.tf32.f32 "
        "{%0,%1,%2,%3}, {%4,%5,%6,%7}, {%8,%9}, {%0,%1,%2,%3};\n"
        : "+f"(d[0]), "+f"(d[1]), "+f"(d[2]), "+f"(d[3])
        : "r"(a[0]), "r"(a[1]), "r"(a[2]), "r"(a[3]), "r"(b[0]), "r"(b[1]));
}

__device__ __forceinline__ float silu_f(float x) {
    return x / (1.0f + expf(-x));
}

// ---------------- kernel 0: zero out + counts -------------------------------
__global__ void init_kernel(float* __restrict__ out) {
    size_t idx = (size_t)blockIdx.x * blockDim.x + threadIdx.x;
    if (idx < E_) g_counts[idx] = 0;
    const size_t total = (size_t)T_ * H_;
    const size_t stride = (size_t)gridDim.x * blockDim.x;
    for (size_t i = idx; i < total; i += stride) out[i] = 0.0f;
}

// ---------------- kernel 1: router (1 block / token, 128 threads) -----------
__global__ void router_kernel(const float* __restrict__ hs, const float* __restrict__ gw) {
    __shared__ float sh[H_];
    __shared__ float slog[E_];
    const int t = blockIdx.x;
    const int tid = threadIdx.x;
    const float* hr = hs + (size_t)t * H_;
    for (int i = tid; i < H_; i += 128) sh[i] = hr[i];
    __syncthreads();

    const int e = tid >> 3;   // 16 experts, 8 threads each
    const int r = tid & 7;
    const float* gr = gw + (size_t)e * H_;
    float s = 0.0f;
    for (int k = r; k < H_; k += 8) s += sh[k] * gr[k];
    s += __shfl_xor_sync(0xffffffffu, s, 4);
    s += __shfl_xor_sync(0xffffffffu, s, 2);
    s += __shfl_xor_sync(0xffffffffu, s, 1);
    if (r == 0) slog[e] = s;
    __syncthreads();

    if (tid == 0) {
        int i0 = 0; float l0 = slog[0];
        for (int i = 1; i < E_; i++) if (slog[i] > l0) { l0 = slog[i]; i0 = i; }
        int i1 = -1; float l1 = -1e30f;
        for (int i = 0; i < E_; i++) if (i != i0 && slog[i] > l1) { l1 = slog[i]; i1 = i; }
        // softmax + top2 + renorm == p1 = exp(l1-l0); w0 = 1/(1+p1)
        float p1 = expf(l1 - l0);
        float inv = 1.0f / (1.0f + p1);
        g_topk_ids[2 * t]     = i0;
        g_topk_ids[2 * t + 1] = i1;
        g_topk_w[2 * t]     = inv;
        g_topk_w[2 * t + 1] = p1 * inv;
        atomicAdd(&g_counts[i0], 1);
        atomicAdd(&g_counts[i1], 1);
    }
}

// ---------------- kernel 2: exclusive scan over 16 counts --------------------
__global__ void scan_kernel() {
    if (threadIdx.x == 0) {
        int acc = 0;
        g_offsets[0] = 0;
        for (int e = 0; e < E_; e++) {
            g_cursor[e] = acc;
            acc += g_counts[e];
            g_offsets[e + 1] = acc;
        }
    }
}

// ---------------- kernel 3: scatter tokens into expert-sorted order ----------
__global__ void scatter_kernel() {
    int t = blockIdx.x * blockDim.x + threadIdx.x;
    if (t >= T_) return;
#pragma unroll
    for (int k = 0; k < 2; k++) {
        int e = g_topk_ids[2 * t + k];
        int pos = atomicAdd(&g_cursor[e], 1);
        g_sorted_tok[pos] = t;
        g_sorted_w[pos]   = g_topk_w[2 * t + k];
    }
}

// ---------------- GEMM tiling constants --------------------------------------
constexpr int BM = 128;
constexpr int BN = 64;
constexpr int BK = 16;
constexpr int AST = BK + 1;   // 17, coprime with 32 -> conflict-free frag loads

// ---------------- kernel 4: gate/up GEMM + fused SwiGLU ----------------------
// grid: (32 m-tiles, 22 n-tiles over I, 16 experts), 256 threads
__global__ __launch_bounds__(256, 2)
void g1_kernel(const float* __restrict__ hs, const float* __restrict__ ws) {
    __shared__ uint32_t As[BM * AST];
    __shared__ uint32_t Bg[BN * AST];
    __shared__ uint32_t Bu[BN * AST];
    __shared__ int      stok[BM];

    const int e    = blockIdx.z;
    const int off  = g_offsets[e];
    const int rows = g_offsets[e + 1] - off;
    const int m0   = blockIdx.x * BM;
    if (m0 >= rows) return;
    const int n0  = blockIdx.y * BN;
    const int tid = threadIdx.x;

    if (tid < BM) {
        int am = m0 + tid;
        stok[tid] = (am < rows) ? g_sorted_tok[off + am] : -1;
    }
    __syncthreads();

    const float* wg = ws + (size_t)e * TI_ * H_ + (size_t)n0 * H_;
    const float* wu = ws + (size_t)e * TI_ * H_ + (size_t)(I_ + n0) * H_;

    // A staging: 512 float4 loads, 2 per thread. idx = tid*2+j -> (row, quad)
    const int ar0 = (tid * 2) >> 2,     aq0 = (tid * 2) & 3;
    const int ar1 = (tid * 2 + 1) >> 2, aq1 = (tid * 2 + 1) & 3;
    const int brw = tid >> 2,           bq  = tid & 3;   // 64 rows x 4 quads
    const int tok0 = stok[ar0];
    const int tok1 = stok[ar1];
    const float* ap0 = hs + (size_t)(tok0 < 0 ? 0 : tok0) * H_ + aq0 * 4;
    const float* ap1 = hs + (size_t)(tok1 < 0 ? 0 : tok1) * H_ + aq1 * 4;
    const float* bgp = wg + (size_t)brw * H_ + bq * 4;
    const float* bup = wu + (size_t)brw * H_ + bq * 4;

    float4 va0, va1, vbg, vbu;
    const float4 z4 = make_float4(0.f, 0.f, 0.f, 0.f);

    // initial fetch + store (k0 = 0)
    va0 = (tok0 >= 0) ? *(const float4*)(ap0) : z4;
    va1 = (tok1 >= 0) ? *(const float4*)(ap1) : z4;
    vbg = *(const float4*)(bgp);
    vbu = *(const float4*)(bup);
    {
        uint32_t* p;
        p = &As[ar0 * AST + aq0 * 4]; p[0]=f2tf32(va0.x); p[1]=f2tf32(va0.y); p[2]=f2tf32(va0.z); p[3]=f2tf32(va0.w);
        p = &As[ar1 * AST + aq1 * 4]; p[0]=f2tf32(va1.x); p[1]=f2tf32(va1.y); p[2]=f2tf32(va1.z); p[3]=f2tf32(va1.w);
        p = &Bg[brw * AST + bq * 4];  p[0]=f2tf32(vbg.x); p[1]=f2tf32(vbg.y); p[2]=f2tf32(vbg.z); p[3]=f2tf32(vbg.w);
        p = &Bu[brw * AST + bq * 4];  p[0]=f2tf32(vbu.x); p[1]=f2tf32(vbu.y); p[2]=f2tf32(vbu.z); p[3]=f2tf32(vbu.w);
    }
    __syncthreads();

    float accG[2][4][4] = {};
    float accU[2][4][4] = {};

    const int lane = tid & 31, warp = tid >> 5;
    const int wm = (warp >> 1) * 32;   // 4 warps along M
    const int wn = (warp & 1) * 32;    // 2 warps along N
    const int grp = lane >> 2, tig = lane & 3;

#pragma unroll 1
    for (int k0 = 0; k0 < H_; k0 += BK) {
        const bool more = (k0 + BK) < H_;
        if (more) {
            const int kn = k0 + BK;
            va0 = (tok0 >= 0) ? *(const float4*)(ap0 + kn) : z4;
            va1 = (tok1 >= 0) ? *(const float4*)(ap1 + kn) : z4;
            vbg = *(const float4*)(bgp + kn);
            vbu = *(const float4*)(bup + kn);
        }
#pragma unroll
        for (int ks = 0; ks < 2; ks++) {
            const int kk = ks * 8;
            uint32_t af[2][4];
#pragma unroll
            for (int mm = 0; mm < 2; mm++) {
                const uint32_t* p = &As[(wm + mm * 16 + grp) * AST + kk + tig];
                af[mm][0] = p[0];
                af[mm][2] = p[4];
                const uint32_t* q = p + 8 * AST;
                af[mm][1] = q[0];
                af[mm][3] = q[4];
            }
#pragma unroll
            for (int nn = 0; nn < 4; nn++) {
                const uint32_t* pb = &Bg[(wn + nn * 8 + grp) * AST + kk + tig];
                uint32_t bg2[2] = { pb[0], pb[4] };
                const uint32_t* pu = &Bu[(wn + nn * 8 + grp) * AST + kk + tig];
                uint32_t bu2[2] = { pu[0], pu[4] };
#pragma unroll
                for (int mm = 0; mm < 2; mm++) {
                    mma_tf32(accG[mm][nn], af[mm], bg2);
                    mma_tf32(accU[mm][nn], af[mm], bu2);
                }
            }
        }
        __syncthreads();
        if (more) {
            uint32_t* p;
            p = &As[ar0 * AST + aq0 * 4]; p[0]=f2tf32(va0.x); p[1]=f2tf32(va0.y); p[2]=f2tf32(va0.z); p[3]=f2tf32(va0.w);
            p = &As[ar1 * AST + aq1 * 4]; p[0]=f2tf32(va1.x); p[1]=f2tf32(va1.y); p[2]=f2tf32(va1.z); p[3]=f2tf32(va1.w);
            p = &Bg[brw * AST + bq * 4];  p[0]=f2tf32(vbg.x); p[1]=f2tf32(vbg.y); p[2]=f2tf32(vbg.z); p[3]=f2tf32(vbg.w);
            p = &Bu[brw * AST + bq * 4];  p[0]=f2tf32(vbu.x); p[1]=f2tf32(vbu.y); p[2]=f2tf32(vbu.z); p[3]=f2tf32(vbu.w);
            __syncthreads();
        }
    }

    // fused SwiGLU epilogue -> hbuf
#pragma unroll
    for (int mm = 0; mm < 2; mm++) {
#pragma unroll
        for (int nn = 0; nn < 4; nn++) {
            const int r = wm + mm * 16 + grp;
            const int c = n0 + wn + nn * 8 + tig * 2;
            const float* G = accG[mm][nn];
            const float* U = accU[mm][nn];
            if (m0 + r < rows) {
                size_t b = (size_t)(off + m0 + r) * I_ + c;
                g_hbuf[b]     = silu_f(G[0]) * U[0];
                g_hbuf[b + 1] = silu_f(G[1]) * U[1];
            }
            if (m0 + r + 8 < rows) {
                size_t b = (size_t)(off + m0 + r + 8) * I_ + c;
                g_hbuf[b]     = silu_f(G[2]) * U[2];
                g_hbuf[b + 1] = silu_f(G[3]) * U[3];
            }
        }
    }
}

// ---------------- kernel 5: down GEMM + weighted scatter-add -----------------
// grid: (32 m-tiles, 32 n-tiles over H, 16 experts), 256 threads
__global__ __launch_bounds__(256, 2)
void g2_kernel(const float* __restrict__ w2s, float* __restrict__ out) {
    __shared__ uint32_t As[BM * AST];
    __shared__ uint32_t Bs[BN * AST];
    __shared__ int      stok[BM];
    __shared__ float    sw[BM];

    const int e    = blockIdx.z;
    const int off  = g_offsets[e];
    const int rows = g_offsets[e + 1] - off;
    const int m0   = blockIdx.x * BM;
    if (m0 >= rows) return;
    const int n0  = blockIdx.y * BN;
    const int tid = threadIdx.x;

    if (tid < BM) {
        int am = m0 + tid;
        bool v = (am < rows);
        stok[tid] = v ? g_sorted_tok[off + am] : -1;
        sw[tid]   = v ? g_sorted_w[off + am]   : 0.0f;
    }
    __syncthreads();

    const float* wb = w2s + (size_t)e * H_ * I_ + (size_t)n0 * I_;

    const int ar0 = (tid * 2) >> 2,     aq0 = (tid * 2) & 3;
    const int ar1 = (tid * 2 + 1) >> 2, aq1 = (tid * 2 + 1) & 3;
    const int brw = tid >> 2,           bq  = tid & 3;
    const bool v0 = (m0 + ar0) < rows;
    const bool v1 = (m0 + ar1) < rows;
    const float* ap0 = g_hbuf + (size_t)(off + (v0 ? m0 + ar0 : 0)) * I_ + aq0 * 4;
    const float* ap1 = g_hbuf + (size_t)(off + (v1 ? m0 + ar1 : 0)) * I_ + aq1 * 4;
    const float* bp  = wb + (size_t)brw * I_ + bq * 4;

    float4 va0, va1, vb;
    const float4 z4 = make_float4(0.f, 0.f, 0.f, 0.f);

    va0 = v0 ? *(const float4*)(ap0) : z4;
    va1 = v1 ? *(const float4*)(ap1) : z4;
    vb  = *(const float4*)(bp);
    {
        uint32_t* p;
        p = &As[ar0 * AST + aq0 * 4]; p[0]=f2tf32(va0.x); p[1]=f2tf32(va0.y); p[2]=f2tf32(va0.z); p[3]=f2tf32(va0.w);
        p = &As[ar1 * AST + aq1 * 4]; p[0]=f2tf32(va1.x); p[1]=f2tf32(va1.y); p[2]=f2tf32(va1.z); p[3]=f2tf32(va1.w);
        p = &Bs[brw * AST + bq * 4];  p[0]=f2tf32(vb.x);  p[1]=f2tf32(vb.y);  p[2]=f2tf32(vb.z);  p[3]=f2tf32(vb.w);
    }
    __syncthreads();

    float acc[2][4][4] = {};

    const int lane = tid & 31, warp = tid >> 5;
    const int wm = (warp >> 1) * 32;
    const int wn = (warp & 1) * 32;
    const int grp = lane >> 2, tig = lane & 3;

#pragma unroll 1
    for (int k0 = 0; k0 < I_; k0 += BK) {
        const bool more = (k0 + BK) < I_;
        if (more) {
            const int kn = k0 + BK;
            va0 = v0 ? *(const float4*)(ap0 + kn) : z4;
            va1 = v1 ? *(const float4*)(ap1 + kn) : z4;
            vb  = *(const float4*)(bp + kn);
        }
#pragma unroll
        for (int ks = 0; ks < 2; ks++) {
            const int kk = ks * 8;
            uint32_t af[2][4];
#pragma unroll
            for (int mm = 0; mm < 2; mm++) {
                const uint32_t* p = &As[(wm + mm * 16 + grp) * AST + kk + tig];
                af[mm][0] = p[0];
                af[mm][2] = p[4];
                const uint32_t* q = p + 8 * AST;
                af[mm][1] = q[0];
                af[mm][3] = q[4];
            }
#pragma unroll
            for (int nn = 0; nn < 4; nn++) {
                const uint32_t* pb = &Bs[(wn + nn * 8 + grp) * AST + kk + tig];
                uint32_t b2[2] = { pb[0], pb[4] };
#pragma unroll
                for (int mm = 0; mm < 2; mm++) {
                    mma_tf32(acc[mm][nn], af[mm], b2);
                }
            }
        }
        __syncthreads();
        if (more) {
            uint32_t* p;
            p = &As[ar0 * AST + aq0 * 4]; p[0]=f2tf32(va0.x); p[1]=f2tf32(va0.y); p[2]=f2tf32(va0.z); p[3]=f2tf32(va0.w);
            p = &As[ar1 * AST + aq1 * 4]; p[0]=f2tf32(va1.x); p[1]=f2tf32(va1.y); p[2]=f2tf32(va1.z); p[3]=f2tf32(va1.w);
            p = &Bs[brw * AST + bq * 4];  p[0]=f2tf32(vb.x);  p[1]=f2tf32(vb.y);  p[2]=f2tf32(vb.z);  p[3]=f2tf32(vb.w);
            __syncthreads();
        }
    }

    // weighted scatter-add epilogue (exactly 2 commutative adds per out element)
#pragma unroll
    for (int mm = 0; mm < 2; mm++) {
#pragma unroll
        for (int nn = 0; nn < 4; nn++) {
            const int r = wm + mm * 16 + grp;
            const int c = n0 + wn + nn * 8 + tig * 2;
            const float* D = acc[mm][nn];
            int t1 = stok[r];
            if (t1 >= 0) {
                float w = sw[r];
                atomicAdd(&out[(size_t)t1 * H_ + c],     w * D[0]);
                atomicAdd(&out[(size_t)t1 * H_ + c + 1], w * D[1]);
            }
            int t2 = stok[r + 8];
            if (t2 >= 0) {
                float w = sw[r + 8];
                atomicAdd(&out[(size_t)t2 * H_ + c],     w * D[2]);
                atomicAdd(&out[(size_t)t2 * H_ + c + 1], w * D[3]);
            }
        }
    }
}

// ---------------- launch -----------------------------------------------------
extern "C" void kernel_launch(void* const* d_in, const int* in_sizes, int n_in,
                              void* d_out, int out_size) {
    const float* hs  = (const float*)d_in[0];   // [T, H]
    const float* gw  = (const float*)d_in[1];   // [E, H]
    const float* ws  = (const float*)d_in[2];   // [E, 2I, H]
    const float* w2s = (const float*)d_in[3];   // [E, H, I]
    float* out = (float*)d_out;                 // [T, H]
    (void)in_sizes; (void)n_in; (void)out_size; // top_k fixed at 2

    init_kernel<<<2048, 256>>>(out);
    router_kernel<<<T_, 128>>>(hs, gw);
    scan_kernel<<<1, 32>>>();
    scatter_kernel<<<(T_ + 255) / 256, 256>>>();
    {
        dim3 grid(32, I_ / BN, E_);   // 32 x 22 x 16
        g1_kernel<<<grid, 256>>>(hs, ws);
    }
    {
        dim3 grid(32, H_ / BN, E_);   // 32 x 32 x 16
        g2_kernel<<<grid, 256>>>(w2s, out);
    }
}

// round 9
// speedup vs baseline: 1.0492x; 1.0492x over previous
#include <cuda_runtime.h>
#include <cstdint>

#define T_  4096
#define H_  2048
#define I_  1408
#define E_  16
#define TI_ 2816            // 2*I
#define SLOTS (T_*2)        // 8192 (token, expert) pairs

// ---------------- scratch (device globals: no allocation allowed) -----------
__device__ int    g_topk_ids[SLOTS];
__device__ float  g_topk_w[SLOTS];
__device__ int    g_counts[E_];
__device__ int    g_offsets[E_ + 1];
__device__ int    g_cursor[E_];
__device__ int    g_sorted_tok[SLOTS];
__device__ float  g_sorted_w[SLOTS];
__device__ float  g_hbuf[(size_t)SLOTS * I_];   // 46 MB intermediate (silu(g)*u)

// ---------------- helpers ---------------------------------------------------
__device__ __forceinline__ uint32_t f2tf32(float x) {
    uint32_t r;
    asm("cvt.rna.tf32.f32 %0, %1;" : "=r"(r) : "f"(x));
    return r;
}

__device__ __forceinline__ void mma_tf32(float d[4], const uint32_t a[4], const uint32_t b[2]) {
    asm volatile(
        "mma.sync.aligned.m16n8k8.row.col.f32.tf32.tf32.f32 "
        "{%0,%1,%2,%3}, {%4,%5,%6,%7}, {%8,%9}, {%0,%1,%2,%3};\n"
        : "+f"(d[0]), "+f"(d[1]), "+f"(d[2]), "+f"(d[3])
        : "r"(a[0]), "r"(a[1]), "r"(a[2]), "r"(a[3]), "r"(b[0]), "r"(b[1]));
}

__device__ __forceinline__ float silu_f(float x) {
    return x / (1.0f + expf(-x));
}

// ---------------- kernel 0: zero out + counts -------------------------------
__global__ void init_kernel(float* __restrict__ out) {
    size_t idx = (size_t)blockIdx.x * blockDim.x + threadIdx.x;
    if (idx < E_) g_counts[idx] = 0;
    const size_t total = (size_t)T_ * H_;
    const size_t stride = (size_t)gridDim.x * blockDim.x;
    for (size_t i = idx; i < total; i += stride) out[i] = 0.0f;
}

// ---------------- kernel 1: router (1 block / token, 128 threads) -----------
__global__ void router_kernel(const float* __restrict__ hs, const float* __restrict__ gw) {
    __shared__ float sh[H_];
    __shared__ float slog[E_];
    const int t = blockIdx.x;
    const int tid = threadIdx.x;
    const float* hr = hs + (size_t)t * H_;
    for (int i = tid; i < H_; i += 128) sh[i] = hr[i];
    __syncthreads();

    const int e = tid >> 3;   // 16 experts, 8 threads each
    const int r = tid & 7;
    const float* gr = gw + (size_t)e * H_;
    float s = 0.0f;
    for (int k = r; k < H_; k += 8) s += sh[k] * gr[k];
    s += __shfl_xor_sync(0xffffffffu, s, 4);
    s += __shfl_xor_sync(0xffffffffu, s, 2);
    s += __shfl_xor_sync(0xffffffffu, s, 1);
    if (r == 0) slog[e] = s;
    __syncthreads();

    if (tid == 0) {
        int i0 = 0; float l0 = slog[0];
        for (int i = 1; i < E_; i++) if (slog[i] > l0) { l0 = slog[i]; i0 = i; }
        int i1 = -1; float l1 = -1e30f;
        for (int i = 0; i < E_; i++) if (i != i0 && slog[i] > l1) { l1 = slog[i]; i1 = i; }
        float p1 = expf(l1 - l0);
        float inv = 1.0f / (1.0f + p1);
        g_topk_ids[2 * t]     = i0;
        g_topk_ids[2 * t + 1] = i1;
        g_topk_w[2 * t]     = inv;
        g_topk_w[2 * t + 1] = p1 * inv;
        atomicAdd(&g_counts[i0], 1);
        atomicAdd(&g_counts[i1], 1);
    }
}

// ---------------- kernel 2: exclusive scan over 16 counts --------------------
__global__ void scan_kernel() {
    if (threadIdx.x == 0) {
        int acc = 0;
        g_offsets[0] = 0;
        for (int e = 0; e < E_; e++) {
            g_cursor[e] = acc;
            acc += g_counts[e];
            g_offsets[e + 1] = acc;
        }
    }
}

// ---------------- kernel 3: scatter tokens into expert-sorted order ----------
__global__ void scatter_kernel() {
    int t = blockIdx.x * blockDim.x + threadIdx.x;
    if (t >= T_) return;
#pragma unroll
    for (int k = 0; k < 2; k++) {
        int e = g_topk_ids[2 * t + k];
        int pos = atomicAdd(&g_cursor[e], 1);
        g_sorted_tok[pos] = t;
        g_sorted_w[pos]   = g_topk_w[2 * t + k];
    }
}

// ---------------- GEMM tiling constants --------------------------------------
constexpr int BM = 128;
constexpr int BN = 64;
constexpr int BK = 16;
constexpr int AST = BK + 1;   // 17, coprime with 32 -> conflict-free frag loads

// ---------------- kernel 4: gate/up GEMM + fused SwiGLU ----------------------
// Double-buffered smem pipeline: one __syncthreads per BK iteration; the STS
// of stage s+1 overlaps the MMA/LDS of stage s across warps.
// grid: (32 m-tiles, 22 n-tiles over I, 16 experts), 256 threads
__global__ __launch_bounds__(256, 2)
void g1_kernel(const float* __restrict__ hs, const float* __restrict__ ws) {
    __shared__ uint32_t As[2][BM * AST];
    __shared__ uint32_t Bg[2][BN * AST];
    __shared__ uint32_t Bu[2][BN * AST];
    __shared__ int      stok[BM];

    const int e    = blockIdx.z;
    const int off  = g_offsets[e];
    const int rows = g_offsets[e + 1] - off;
    const int m0   = blockIdx.x * BM;
    if (m0 >= rows) return;
    const int n0  = blockIdx.y * BN;
    const int tid = threadIdx.x;

    if (tid < BM) {
        int am = m0 + tid;
        stok[tid] = (am < rows) ? g_sorted_tok[off + am] : -1;
    }
    __syncthreads();

    const float* wg = ws + (size_t)e * TI_ * H_ + (size_t)n0 * H_;
    const float* wu = ws + (size_t)e * TI_ * H_ + (size_t)(I_ + n0) * H_;

    const int ar0 = (tid * 2) >> 2,     aq0 = (tid * 2) & 3;
    const int ar1 = (tid * 2 + 1) >> 2, aq1 = (tid * 2 + 1) & 3;
    const int brw = tid >> 2,           bq  = tid & 3;
    const int tok0 = stok[ar0];
    const int tok1 = stok[ar1];
    const float* ap0 = hs + (size_t)(tok0 < 0 ? 0 : tok0) * H_ + aq0 * 4;
    const float* ap1 = hs + (size_t)(tok1 < 0 ? 0 : tok1) * H_ + aq1 * 4;
    const float* bgp = wg + (size_t)brw * H_ + bq * 4;
    const float* bup = wu + (size_t)brw * H_ + bq * 4;

    float4 va0, va1, vbg, vbu;
    const float4 z4 = make_float4(0.f, 0.f, 0.f, 0.f);

    float accG[2][4][4] = {};
    float accU[2][4][4] = {};

    const int lane = tid & 31, warp = tid >> 5;
    const int wm = (warp >> 1) * 32;   // 4 warps along M
    const int wn = (warp & 1) * 32;    // 2 warps along N
    const int grp = lane >> 2, tig = lane & 3;

    auto fetch = [&](int kn) {
        va0 = (tok0 >= 0) ? *(const float4*)(ap0 + kn) : z4;
        va1 = (tok1 >= 0) ? *(const float4*)(ap1 + kn) : z4;
        vbg = *(const float4*)(bgp + kn);
        vbu = *(const float4*)(bup + kn);
    };
    auto stage = [&](int b) {
        uint32_t* p;
        p = &As[b][ar0 * AST + aq0 * 4]; p[0]=f2tf32(va0.x); p[1]=f2tf32(va0.y); p[2]=f2tf32(va0.z); p[3]=f2tf32(va0.w);
        p = &As[b][ar1 * AST + aq1 * 4]; p[0]=f2tf32(va1.x); p[1]=f2tf32(va1.y); p[2]=f2tf32(va1.z); p[3]=f2tf32(va1.w);
        p = &Bg[b][brw * AST + bq * 4];  p[0]=f2tf32(vbg.x); p[1]=f2tf32(vbg.y); p[2]=f2tf32(vbg.z); p[3]=f2tf32(vbg.w);
        p = &Bu[b][brw * AST + bq * 4];  p[0]=f2tf32(vbu.x); p[1]=f2tf32(vbu.y); p[2]=f2tf32(vbu.z); p[3]=f2tf32(vbu.w);
    };
    auto compute = [&](int b) {
#pragma unroll
        for (int ks = 0; ks < 2; ks++) {
            const int kk = ks * 8;
            uint32_t af[2][4];
#pragma unroll
            for (int mm = 0; mm < 2; mm++) {
                const uint32_t* p = &As[b][(wm + mm * 16 + grp) * AST + kk + tig];
                af[mm][0] = p[0];
                af[mm][2] = p[4];
                const uint32_t* q = p + 8 * AST;
                af[mm][1] = q[0];
                af[mm][3] = q[4];
            }
#pragma unroll
            for (int nn = 0; nn < 4; nn++) {
                const uint32_t* pb = &Bg[b][(wn + nn * 8 + grp) * AST + kk + tig];
                uint32_t bg2[2] = { pb[0], pb[4] };
                const uint32_t* pu = &Bu[b][(wn + nn * 8 + grp) * AST + kk + tig];
                uint32_t bu2[2] = { pu[0], pu[4] };
#pragma unroll
                for (int mm = 0; mm < 2; mm++) {
                    mma_tf32(accG[mm][nn], af[mm], bg2);
                    mma_tf32(accU[mm][nn], af[mm], bu2);
                }
            }
        }
    };

    // prologue: fill buffer 0
    fetch(0);
    stage(0);
    __syncthreads();

    constexpr int NS = H_ / BK;   // 128 (even)
#pragma unroll 1
    for (int s = 0; s < NS; s += 2) {
        // iter s: compute buf0, stage s+1 into buf1 (s+1 < NS always here)
        fetch((s + 1) * BK);
        compute(0);
        stage(1);
        __syncthreads();
        // iter s+1: compute buf1, stage s+2 into buf0 (unless done)
        const bool more = (s + 2) < NS;
        if (more) fetch((s + 2) * BK);
        compute(1);
        if (more) {
            stage(0);
            __syncthreads();
        }
    }

    // fused SwiGLU epilogue -> hbuf
#pragma unroll
    for (int mm = 0; mm < 2; mm++) {
#pragma unroll
        for (int nn = 0; nn < 4; nn++) {
            const int r = wm + mm * 16 + grp;
            const int c = n0 + wn + nn * 8 + tig * 2;
            const float* G = accG[mm][nn];
            const float* U = accU[mm][nn];
            if (m0 + r < rows) {
                size_t b = (size_t)(off + m0 + r) * I_ + c;
                g_hbuf[b]     = silu_f(G[0]) * U[0];
                g_hbuf[b + 1] = silu_f(G[1]) * U[1];
            }
            if (m0 + r + 8 < rows) {
                size_t b = (size_t)(off + m0 + r + 8) * I_ + c;
                g_hbuf[b]     = silu_f(G[2]) * U[2];
                g_hbuf[b + 1] = silu_f(G[3]) * U[3];
            }
        }
    }
}

// ---------------- kernel 5: down GEMM + weighted scatter-add -----------------
// Same double-buffered pipeline.
// grid: (32 m-tiles, 32 n-tiles over H, 16 experts), 256 threads
__global__ __launch_bounds__(256, 2)
void g2_kernel(const float* __restrict__ w2s, float* __restrict__ out) {
    __shared__ uint32_t As[2][BM * AST];
    __shared__ uint32_t Bs[2][BN * AST];
    __shared__ int      stok[BM];
    __shared__ float    sw[BM];

    const int e    = blockIdx.z;
    const int off  = g_offsets[e];
    const int rows = g_offsets[e + 1] - off;
    const int m0   = blockIdx.x * BM;
    if (m0 >= rows) return;
    const int n0  = blockIdx.y * BN;
    const int tid = threadIdx.x;

    if (tid < BM) {
        int am = m0 + tid;
        bool v = (am < rows);
        stok[tid] = v ? g_sorted_tok[off + am] : -1;
        sw[tid]   = v ? g_sorted_w[off + am]   : 0.0f;
    }
    __syncthreads();

    const float* wb = w2s + (size_t)e * H_ * I_ + (size_t)n0 * I_;

    const int ar0 = (tid * 2) >> 2,     aq0 = (tid * 2) & 3;
    const int ar1 = (tid * 2 + 1) >> 2, aq1 = (tid * 2 + 1) & 3;
    const int brw = tid >> 2,           bq  = tid & 3;
    const bool v0 = (m0 + ar0) < rows;
    const bool v1 = (m0 + ar1) < rows;
    const float* ap0 = g_hbuf + (size_t)(off + (v0 ? m0 + ar0 : 0)) * I_ + aq0 * 4;
    const float* ap1 = g_hbuf + (size_t)(off + (v1 ? m0 + ar1 : 0)) * I_ + aq1 * 4;
    const float* bp  = wb + (size_t)brw * I_ + bq * 4;

    float4 va0, va1, vb;
    const float4 z4 = make_float4(0.f, 0.f, 0.f, 0.f);

    float acc[2][4][4] = {};

    const int lane = tid & 31, warp = tid >> 5;
    const int wm = (warp >> 1) * 32;
    const int wn = (warp & 1) * 32;
    const int grp = lane >> 2, tig = lane & 3;

    auto fetch = [&](int kn) {
        va0 = v0 ? *(const float4*)(ap0 + kn) : z4;
        va1 = v1 ? *(const float4*)(ap1 + kn) : z4;
        vb  = *(const float4*)(bp + kn);
    };
    auto stage = [&](int b) {
        uint32_t* p;
        p = &As[b][ar0 * AST + aq0 * 4]; p[0]=f2tf32(va0.x); p[1]=f2tf32(va0.y); p[2]=f2tf32(va0.z); p[3]=f2tf32(va0.w);
        p = &As[b][ar1 * AST + aq1 * 4]; p[0]=f2tf32(va1.x); p[1]=f2tf32(va1.y); p[2]=f2tf32(va1.z); p[3]=f2tf32(va1.w);
        p = &Bs[b][brw * AST + bq * 4];  p[0]=f2tf32(vb.x);  p[1]=f2tf32(vb.y);  p[2]=f2tf32(vb.z);  p[3]=f2tf32(vb.w);
    };
    auto compute = [&](int b) {
#pragma unroll
        for (int ks = 0; ks < 2; ks++) {
            const int kk = ks * 8;
            uint32_t af[2][4];
#pragma unroll
            for (int mm = 0; mm < 2; mm++) {
                const uint32_t* p = &As[b][(wm + mm * 16 + grp) * AST + kk + tig];
                af[mm][0] = p[0];
                af[mm][2] = p[4];
                const uint32_t* q = p + 8 * AST;
                af[mm][1] = q[0];
                af[mm][3] = q[4];
            }
#pragma unroll
            for (int nn = 0; nn < 4; nn++) {
                const uint32_t* pb = &Bs[b][(wn + nn * 8 + grp) * AST + kk + tig];
                uint32_t b2[2] = { pb[0], pb[4] };
#pragma unroll
                for (int mm = 0; mm < 2; mm++) {
                    mma_tf32(acc[mm][nn], af[mm], b2);
                }
            }
        }
    };

    fetch(0);
    stage(0);
    __syncthreads();

    constexpr int NS = I_ / BK;   // 88 (even)
#pragma unroll 1
    for (int s = 0; s < NS; s += 2) {
        fetch((s + 1) * BK);
        compute(0);
        stage(1);
        __syncthreads();
        const bool more = (s + 2) < NS;
        if (more) fetch((s + 2) * BK);
        compute(1);
        if (more) {
            stage(0);
            __syncthreads();
        }
    }

    // weighted scatter-add epilogue (exactly 2 commutative adds per out element)
#pragma unroll
    for (int mm = 0; mm < 2; mm++) {
#pragma unroll
        for (int nn = 0; nn < 4; nn++) {
            const int r = wm + mm * 16 + grp;
            const int c = n0 + wn + nn * 8 + tig * 2;
            const float* D = acc[mm][nn];
            int t1 = stok[r];
            if (t1 >= 0) {
                float w = sw[r];
                atomicAdd(&out[(size_t)t1 * H_ + c],     w * D[0]);
                atomicAdd(&out[(size_t)t1 * H_ + c + 1], w * D[1]);
            }
            int t2 = stok[r + 8];
            if (t2 >= 0) {
                float w = sw[r + 8];
                atomicAdd(&out[(size_t)t2 * H_ + c],     w * D[2]);
                atomicAdd(&out[(size_t)t2 * H_ + c + 1], w * D[3]);
            }
        }
    }
}

// ---------------- launch -----------------------------------------------------
extern "C" void kernel_launch(void* const* d_in, const int* in_sizes, int n_in,
                              void* d_out, int out_size) {
    const float* hs  = (const float*)d_in[0];   // [T, H]
    const float* gw  = (const float*)d_in[1];   // [E, H]
    const float* ws  = (const float*)d_in[2];   // [E, 2I, H]
    const float* w2s = (const float*)d_in[3];   // [E, H, I]
    float* out = (float*)d_out;                 // [T, H]
    (void)in_sizes; (void)n_in; (void)out_size; // top_k fixed at 2

    init_kernel<<<2048, 256>>>(out);
    router_kernel<<<T_, 128>>>(hs, gw);
    scan_kernel<<<1, 32>>>();
    scatter_kernel<<<(T_ + 255) / 256, 256>>>();
    {
        dim3 grid(32, I_ / BN, E_);   // 32 x 22 x 16
        g1_kernel<<<grid, 256>>>(hs, ws);
    }
    {
        dim3 grid(32, H_ / BN, E_);   // 32 x 32 x 16
        g2_kernel<<<grid, 256>>>(w2s, out);
    }
}

// round 12
// speedup vs baseline: 1.6423x; 1.5652x over previous
#include <cuda_runtime.h>
#include <cuda_fp16.h>
#include <cstdint>

#define T_  4096
#define H_  2048
#define I_  1408
#define E_  16
#define TI_ 2816            // 2*I
#define SLOTS (T_*2)        // 8192 (token, expert) pairs

// ---------------- scratch (device globals: no allocation allowed) -----------
__device__ int    g_topk_ids[SLOTS];
__device__ float  g_topk_w[SLOTS];
__device__ int    g_counts[E_];
__device__ int    g_offsets[E_ + 1];
__device__ int    g_cursor[E_];
__device__ int    g_sorted_tok[SLOTS];
__device__ float  g_sorted_w[SLOTS];
__device__ float  g_hbuf[(size_t)SLOTS * I_];   // 46 MB intermediate (silu(g)*u)

// ---------------- helpers ---------------------------------------------------
// fp16 MMA: D(16x8,f32) += A(16x16,f16,row) * B(16x8,f16,col)
__device__ __forceinline__ void mma_f16(float d[4], const uint32_t a[4], const uint32_t b[2]) {
    asm volatile(
        "mma.sync.aligned.m16n8k16.row.col.f32.f16.f16.f32 "
        "{%0,%1,%2,%3}, {%4,%5,%6,%7}, {%8,%9}, {%0,%1,%2,%3};\n"
        : "+f"(d[0]), "+f"(d[1]), "+f"(d[2]), "+f"(d[3])
        : "r"(a[0]), "r"(a[1]), "r"(a[2]), "r"(a[3]), "r"(b[0]), "r"(b[1]));
}

__device__ __forceinline__ uint32_t pack_h2(float lo, float hi) {
    __half2 h = __floats2half2_rn(lo, hi);   // .x = lo -> low 16 bits
    return *(uint32_t*)&h;
}

__device__ __forceinline__ float silu_f(float x) {
    return x / (1.0f + expf(-x));
}

// ---------------- kernel 0: zero out + counts -------------------------------
__global__ void init_kernel(float* __restrict__ out) {
    size_t idx = (size_t)blockIdx.x * blockDim.x + threadIdx.x;
    if (idx < E_) g_counts[idx] = 0;
    const size_t total = (size_t)T_ * H_;
    const size_t stride = (size_t)gridDim.x * blockDim.x;
    for (size_t i = idx; i < total; i += stride) out[i] = 0.0f;
}

// ---------------- kernel 1: router (1 block / token, 128 threads) -----------
__global__ void router_kernel(const float* __restrict__ hs, const float* __restrict__ gw) {
    __shared__ float sh[H_];
    __shared__ float slog[E_];
    const int t = blockIdx.x;
    const int tid = threadIdx.x;
    const float* hr = hs + (size_t)t * H_;
    for (int i = tid; i < H_; i += 128) sh[i] = hr[i];
    __syncthreads();

    const int e = tid >> 3;   // 16 experts, 8 threads each
    const int r = tid & 7;
    const float* gr = gw + (size_t)e * H_;
    float s = 0.0f;
    for (int k = r; k < H_; k += 8) s += sh[k] * gr[k];
    s += __shfl_xor_sync(0xffffffffu, s, 4);
    s += __shfl_xor_sync(0xffffffffu, s, 2);
    s += __shfl_xor_sync(0xffffffffu, s, 1);
    if (r == 0) slog[e] = s;
    __syncthreads();

    if (tid == 0) {
        int i0 = 0; float l0 = slog[0];
        for (int i = 1; i < E_; i++) if (slog[i] > l0) { l0 = slog[i]; i0 = i; }
        int i1 = -1; float l1 = -1e30f;
        for (int i = 0; i < E_; i++) if (i != i0 && slog[i] > l1) { l1 = slog[i]; i1 = i; }
        float p1 = expf(l1 - l0);
        float inv = 1.0f / (1.0f + p1);
        g_topk_ids[2 * t]     = i0;
        g_topk_ids[2 * t + 1] = i1;
        g_topk_w[2 * t]     = inv;
        g_topk_w[2 * t + 1] = p1 * inv;
        atomicAdd(&g_counts[i0], 1);
        atomicAdd(&g_counts[i1], 1);
    }
}

// ---------------- kernel 2: exclusive scan over 16 counts --------------------
__global__ void scan_kernel() {
    if (threadIdx.x == 0) {
        int acc = 0;
        g_offsets[0] = 0;
        for (int e = 0; e < E_; e++) {
            g_cursor[e] = acc;
            acc += g_counts[e];
            g_offsets[e + 1] = acc;
        }
    }
}

// ---------------- kernel 3: scatter tokens into expert-sorted order ----------
__global__ void scatter_kernel() {
    int t = blockIdx.x * blockDim.x + threadIdx.x;
    if (t >= T_) return;
#pragma unroll
    for (int k = 0; k < 2; k++) {
        int e = g_topk_ids[2 * t + k];
        int pos = atomicAdd(&g_cursor[e], 1);
        g_sorted_tok[pos] = t;
        g_sorted_w[pos]   = g_topk_w[2 * t + k];
    }
}

// ---------------- GEMM tiling constants --------------------------------------
// fp16 path: BK=16 halves per stage = 8 u32 (half2) per row; row stride 12 u32
// -> fragment loads at (12*grp + tig) and (+4) hit all 32 banks, conflict-free.
constexpr int BM = 128;
constexpr int BN = 64;
constexpr int BK = 16;
constexpr int AST = 12;     // u32 stride per row (8 used + 4 pad)

// ---------------- kernel 4: gate/up GEMM + fused SwiGLU ----------------------
// Double-buffered; one __syncthreads per BK iteration.
// grid: (32 m-tiles, 22 n-tiles over I, 16 experts), 256 threads
__global__ __launch_bounds__(256, 2)
void g1_kernel(const float* __restrict__ hs, const float* __restrict__ ws) {
    __shared__ uint32_t As[2][BM * AST];
    __shared__ uint32_t Bg[2][BN * AST];
    __shared__ uint32_t Bu[2][BN * AST];
    __shared__ int      stok[BM];

    const int e    = blockIdx.z;
    const int off  = g_offsets[e];
    const int rows = g_offsets[e + 1] - off;
    const int m0   = blockIdx.x * BM;
    if (m0 >= rows) return;
    const int n0  = blockIdx.y * BN;
    const int tid = threadIdx.x;

    if (tid < BM) {
        int am = m0 + tid;
        stok[tid] = (am < rows) ? g_sorted_tok[off + am] : -1;
    }
    __syncthreads();

    const float* wg = ws + (size_t)e * TI_ * H_ + (size_t)n0 * H_;
    const float* wu = ws + (size_t)e * TI_ * H_ + (size_t)(I_ + n0) * H_;

    // A: 128 rows x 4 quads (16 floats/row) = 512 float4, 2 per thread
    const int ar0 = (tid * 2) >> 2,     aq0 = (tid * 2) & 3;
    const int ar1 = (tid * 2 + 1) >> 2, aq1 = (tid * 2 + 1) & 3;
    // B: 64 rows x 4 quads = 256 float4, 1 per thread (for each of Bg, Bu)
    const int brw = tid >> 2,           bq  = tid & 3;
    const int tok0 = stok[ar0];
    const int tok1 = stok[ar1];
    const float* ap0 = hs + (size_t)(tok0 < 0 ? 0 : tok0) * H_ + aq0 * 4;
    const float* ap1 = hs + (size_t)(tok1 < 0 ? 0 : tok1) * H_ + aq1 * 4;
    const float* bgp = wg + (size_t)brw * H_ + bq * 4;
    const float* bup = wu + (size_t)brw * H_ + bq * 4;

    float4 va0, va1, vbg, vbu;
    const float4 z4 = make_float4(0.f, 0.f, 0.f, 0.f);

    float accG[2][4][4] = {};
    float accU[2][4][4] = {};

    const int lane = tid & 31, warp = tid >> 5;
    const int wm = (warp >> 1) * 32;   // 4 warps along M
    const int wn = (warp & 1) * 32;    // 2 warps along N
    const int grp = lane >> 2, tig = lane & 3;

    auto fetch = [&](int kn) {
        va0 = (tok0 >= 0) ? *(const float4*)(ap0 + kn) : z4;
        va1 = (tok1 >= 0) ? *(const float4*)(ap1 + kn) : z4;
        vbg = *(const float4*)(bgp + kn);
        vbu = *(const float4*)(bup + kn);
    };
    auto stage = [&](int b) {
        uint32_t* p;
        p = &As[b][ar0 * AST + aq0 * 2]; p[0] = pack_h2(va0.x, va0.y); p[1] = pack_h2(va0.z, va0.w);
        p = &As[b][ar1 * AST + aq1 * 2]; p[0] = pack_h2(va1.x, va1.y); p[1] = pack_h2(va1.z, va1.w);
        p = &Bg[b][brw * AST + bq * 2];  p[0] = pack_h2(vbg.x, vbg.y); p[1] = pack_h2(vbg.z, vbg.w);
        p = &Bu[b][brw * AST + bq * 2];  p[0] = pack_h2(vbu.x, vbu.y); p[1] = pack_h2(vbu.z, vbu.w);
    };
    auto compute = [&](int b) {
        uint32_t af[2][4];
#pragma unroll
        for (int mm = 0; mm < 2; mm++) {
            const uint32_t* p = &As[b][(wm + mm * 16 + grp) * AST + tig];
            const uint32_t* q = p + 8 * AST;
            af[mm][0] = p[0];   // row grp,   k0-7
            af[mm][1] = q[0];   // row grp+8, k0-7
            af[mm][2] = p[4];   // row grp,   k8-15
            af[mm][3] = q[4];   // row grp+8, k8-15
        }
#pragma unroll
        for (int nn = 0; nn < 4; nn++) {
            const uint32_t* pb = &Bg[b][(wn + nn * 8 + grp) * AST + tig];
            uint32_t bg2[2] = { pb[0], pb[4] };
            const uint32_t* pu = &Bu[b][(wn + nn * 8 + grp) * AST + tig];
            uint32_t bu2[2] = { pu[0], pu[4] };
#pragma unroll
            for (int mm = 0; mm < 2; mm++) {
                mma_f16(accG[mm][nn], af[mm], bg2);
                mma_f16(accU[mm][nn], af[mm], bu2);
            }
        }
    };

    // prologue
    fetch(0);
    stage(0);
    __syncthreads();

    constexpr int NS = H_ / BK;   // 128 (even)
#pragma unroll 1
    for (int s = 0; s < NS; s += 2) {
        fetch((s + 1) * BK);
        compute(0);
        stage(1);
        __syncthreads();
        const bool more = (s + 2) < NS;
        if (more) fetch((s + 2) * BK);
        compute(1);
        if (more) {
            stage(0);
            __syncthreads();
        }
    }

    // fused SwiGLU epilogue -> hbuf (C/D layout identical to tf32 path)
#pragma unroll
    for (int mm = 0; mm < 2; mm++) {
#pragma unroll
        for (int nn = 0; nn < 4; nn++) {
            const int r = wm + mm * 16 + grp;
            const int c = n0 + wn + nn * 8 + tig * 2;
            const float* G = accG[mm][nn];
            const float* U = accU[mm][nn];
            if (m0 + r < rows) {
                size_t b = (size_t)(off + m0 + r) * I_ + c;
                g_hbuf[b]     = silu_f(G[0]) * U[0];
                g_hbuf[b + 1] = silu_f(G[1]) * U[1];
            }
            if (m0 + r + 8 < rows) {
                size_t b = (size_t)(off + m0 + r + 8) * I_ + c;
                g_hbuf[b]     = silu_f(G[2]) * U[2];
                g_hbuf[b + 1] = silu_f(G[3]) * U[3];
            }
        }
    }
}

// ---------------- kernel 5: down GEMM + weighted scatter-add -----------------
// grid: (32 m-tiles, 32 n-tiles over H, 16 experts), 256 threads
__global__ __launch_bounds__(256, 2)
void g2_kernel(const float* __restrict__ w2s, float* __restrict__ out) {
    __shared__ uint32_t As[2][BM * AST];
    __shared__ uint32_t Bs[2][BN * AST];
    __shared__ int      stok[BM];
    __shared__ float    sw[BM];

    const int e    = blockIdx.z;
    const int off  = g_offsets[e];
    const int rows = g_offsets[e + 1] - off;
    const int m0   = blockIdx.x * BM;
    if (m0 >= rows) return;
    const int n0  = blockIdx.y * BN;
    const int tid = threadIdx.x;

    if (tid < BM) {
        int am = m0 + tid;
        bool v = (am < rows);
        stok[tid] = v ? g_sorted_tok[off + am] : -1;
        sw[tid]   = v ? g_sorted_w[off + am]   : 0.0f;
    }
    __syncthreads();

    const float* wb = w2s + (size_t)e * H_ * I_ + (size_t)n0 * I_;

    const int ar0 = (tid * 2) >> 2,     aq0 = (tid * 2) & 3;
    const int ar1 = (tid * 2 + 1) >> 2, aq1 = (tid * 2 + 1) & 3;
    const int brw = tid >> 2,           bq  = tid & 3;
    const bool v0 = (m0 + ar0) < rows;
    const bool v1 = (m0 + ar1) < rows;
    const float* ap0 = g_hbuf + (size_t)(off + (v0 ? m0 + ar0 : 0)) * I_ + aq0 * 4;
    const float* ap1 = g_hbuf + (size_t)(off + (v1 ? m0 + ar1 : 0)) * I_ + aq1 * 4;
    const float* bp  = wb + (size_t)brw * I_ + bq * 4;

    float4 va0, va1, vb;
    const float4 z4 = make_float4(0.f, 0.f, 0.f, 0.f);

    float acc[2][4][4] = {};

    const int lane = tid & 31, warp = tid >> 5;
    const int wm = (warp >> 1) * 32;
    const int wn = (warp & 1) * 32;
    const int grp = lane >> 2, tig = lane & 3;

    auto fetch = [&](int kn) {
        va0 = v0 ? *(const float4*)(ap0 + kn) : z4;
        va1 = v1 ? *(const float4*)(ap1 + kn) : z4;
        vb  = *(const float4*)(bp + kn);
    };
    auto stage = [&](int b) {
        uint32_t* p;
        p = &As[b][ar0 * AST + aq0 * 2]; p[0] = pack_h2(va0.x, va0.y); p[1] = pack_h2(va0.z, va0.w);
        p = &As[b][ar1 * AST + aq1 * 2]; p[0] = pack_h2(va1.x, va1.y); p[1] = pack_h2(va1.z, va1.w);
        p = &Bs[b][brw * AST + bq * 2];  p[0] = pack_h2(vb.x, vb.y);   p[1] = pack_h2(vb.z, vb.w);
    };
    auto compute = [&](int b) {
        uint32_t af[2][4];
#pragma unroll
        for (int mm = 0; mm < 2; mm++) {
            const uint32_t* p = &As[b][(wm + mm * 16 + grp) * AST + tig];
            const uint32_t* q = p + 8 * AST;
            af[mm][0] = p[0];
            af[mm][1] = q[0];
            af[mm][2] = p[4];
            af[mm][3] = q[4];
        }
#pragma unroll
        for (int nn = 0; nn < 4; nn++) {
            const uint32_t* pb = &Bs[b][(wn + nn * 8 + grp) * AST + tig];
            uint32_t b2[2] = { pb[0], pb[4] };
#pragma unroll
            for (int mm = 0; mm < 2; mm++) {
                mma_f16(acc[mm][nn], af[mm], b2);
            }
        }
    };

    fetch(0);
    stage(0);
    __syncthreads();

    constexpr int NS = I_ / BK;   // 88 (even)
#pragma unroll 1
    for (int s = 0; s < NS; s += 2) {
        fetch((s + 1) * BK);
        compute(0);
        stage(1);
        __syncthreads();
        const bool more = (s + 2) < NS;
        if (more) fetch((s + 2) * BK);
        compute(1);
        if (more) {
            stage(0);
            __syncthreads();
        }
    }

    // weighted scatter-add epilogue (exactly 2 commutative adds per out element)
#pragma unroll
    for (int mm = 0; mm < 2; mm++) {
#pragma unroll
        for (int nn = 0; nn < 4; nn++) {
            const int r = wm + mm * 16 + grp;
            const int c = n0 + wn + nn * 8 + tig * 2;
            const float* D = acc[mm][nn];
            int t1 = stok[r];
            if (t1 >= 0) {
                float w = sw[r];
                atomicAdd(&out[(size_t)t1 * H_ + c],     w * D[0]);
                atomicAdd(&out[(size_t)t1 * H_ + c + 1], w * D[1]);
            }
            int t2 = stok[r + 8];
            if (t2 >= 0) {
                float w = sw[r + 8];
                atomicAdd(&out[(size_t)t2 * H_ + c],     w * D[2]);
                atomicAdd(&out[(size_t)t2 * H_ + c + 1], w * D[3]);
            }
        }
    }
}

// ---------------- launch -----------------------------------------------------
extern "C" void kernel_launch(void* const* d_in, const int* in_sizes, int n_in,
                              void* d_out, int out_size) {
    const float* hs  = (const float*)d_in[0];   // [T, H]
    const float* gw  = (const float*)d_in[1];   // [E, H]
    const float* ws  = (const float*)d_in[2];   // [E, 2I, H]
    const float* w2s = (const float*)d_in[3];   // [E, H, I]
    float* out = (float*)d_out;                 // [T, H]
    (void)in_sizes; (void)n_in; (void)out_size; // top_k fixed at 2

    init_kernel<<<2048, 256>>>(out);
    router_kernel<<<T_, 128>>>(hs, gw);
    scan_kernel<<<1, 32>>>();
    scatter_kernel<<<(T_ + 255) / 256, 256>>>();
    {
        dim3 grid(32, I_ / BN, E_);   // 32 x 22 x 16
        g1_kernel<<<grid, 256>>>(hs, ws);
    }
    {
        dim3 grid(32, H_ / BN, E_);   // 32 x 32 x 16
        g2_kernel<<<grid, 256>>>(w2s, out);
    }
}

// round 13
// speedup vs baseline: 1.7535x; 1.0677x over previous
#include <cuda_runtime.h>
#include <cuda_fp16.h>
#include <cstdint>

#define T_  4096
#define H_  2048
#define I_  1408
#define E_  16
#define TI_ 2816            // 2*I
#define SLOTS (T_*2)        // 8192 (token, expert) pairs

// ---------------- scratch (device globals: no allocation allowed) -----------
__device__ int    g_topk_ids[SLOTS];
__device__ float  g_topk_w[SLOTS];
__device__ int    g_counts[E_];
__device__ int    g_offsets[E_ + 1];
__device__ int    g_cursor[E_];
__device__ int    g_sorted_tok[SLOTS];
__device__ float  g_sorted_w[SLOTS];
__device__ float  g_hbuf[(size_t)SLOTS * I_];   // 46 MB intermediate (silu(g)*u)

// ---------------- helpers ---------------------------------------------------
// fp16 MMA: D(16x8,f32) += A(16x16,f16,row) * B(16x8,f16,col)
__device__ __forceinline__ void mma_f16(float d[4], const uint32_t a[4], const uint32_t b[2]) {
    asm volatile(
        "mma.sync.aligned.m16n8k16.row.col.f32.f16.f16.f32 "
        "{%0,%1,%2,%3}, {%4,%5,%6,%7}, {%8,%9}, {%0,%1,%2,%3};\n"
        : "+f"(d[0]), "+f"(d[1]), "+f"(d[2]), "+f"(d[3])
        : "r"(a[0]), "r"(a[1]), "r"(a[2]), "r"(a[3]), "r"(b[0]), "r"(b[1]));
}

// ldmatrix x4: four 8x8 b16 matrices; lane 8j+r supplies row-address r of matrix j
__device__ __forceinline__ void ldsm_x4(uint32_t r[4], uint32_t saddr) {
    asm volatile("ldmatrix.sync.aligned.m8n8.x4.shared.b16 {%0,%1,%2,%3}, [%4];"
                 : "=r"(r[0]), "=r"(r[1]), "=r"(r[2]), "=r"(r[3]) : "r"(saddr));
}

__device__ __forceinline__ uint32_t pack_h2(float lo, float hi) {
    __half2 h = __floats2half2_rn(lo, hi);   // .x = lo -> low 16 bits
    return *(uint32_t*)&h;
}

__device__ __forceinline__ float silu_f(float x) {
    return x / (1.0f + expf(-x));
}

// ---------------- kernel 0: zero out + counts -------------------------------
__global__ void init_kernel(float* __restrict__ out) {
    size_t idx = (size_t)blockIdx.x * blockDim.x + threadIdx.x;
    if (idx < E_) g_counts[idx] = 0;
    const size_t total = (size_t)T_ * H_;
    const size_t stride = (size_t)gridDim.x * blockDim.x;
    for (size_t i = idx; i < total; i += stride) out[i] = 0.0f;
}

// ---------------- kernel 1: router (1 block / token, 128 threads) -----------
__global__ void router_kernel(const float* __restrict__ hs, const float* __restrict__ gw) {
    __shared__ float sh[H_];
    __shared__ float slog[E_];
    const int t = blockIdx.x;
    const int tid = threadIdx.x;
    const float* hr = hs + (size_t)t * H_;
    for (int i = tid; i < H_; i += 128) sh[i] = hr[i];
    __syncthreads();

    const int e = tid >> 3;   // 16 experts, 8 threads each
    const int r = tid & 7;
    const float* gr = gw + (size_t)e * H_;
    float s = 0.0f;
    for (int k = r; k < H_; k += 8) s += sh[k] * gr[k];
    s += __shfl_xor_sync(0xffffffffu, s, 4);
    s += __shfl_xor_sync(0xffffffffu, s, 2);
    s += __shfl_xor_sync(0xffffffffu, s, 1);
    if (r == 0) slog[e] = s;
    __syncthreads();

    if (tid == 0) {
        int i0 = 0; float l0 = slog[0];
        for (int i = 1; i < E_; i++) if (slog[i] > l0) { l0 = slog[i]; i0 = i; }
        int i1 = -1; float l1 = -1e30f;
        for (int i = 0; i < E_; i++) if (i != i0 && slog[i] > l1) { l1 = slog[i]; i1 = i; }
        float p1 = expf(l1 - l0);
        float inv = 1.0f / (1.0f + p1);
        g_topk_ids[2 * t]     = i0;
        g_topk_ids[2 * t + 1] = i1;
        g_topk_w[2 * t]     = inv;
        g_topk_w[2 * t + 1] = p1 * inv;
        atomicAdd(&g_counts[i0], 1);
        atomicAdd(&g_counts[i1], 1);
    }
}

// ---------------- kernel 2: exclusive scan over 16 counts --------------------
__global__ void scan_kernel() {
    if (threadIdx.x == 0) {
        int acc = 0;
        g_offsets[0] = 0;
        for (int e = 0; e < E_; e++) {
            g_cursor[e] = acc;
            acc += g_counts[e];
            g_offsets[e + 1] = acc;
        }
    }
}

// ---------------- kernel 3: scatter tokens into expert-sorted order ----------
__global__ void scatter_kernel() {
    int t = blockIdx.x * blockDim.x + threadIdx.x;
    if (t >= T_) return;
#pragma unroll
    for (int k = 0; k < 2; k++) {
        int e = g_topk_ids[2 * t + k];
        int pos = atomicAdd(&g_cursor[e], 1);
        g_sorted_tok[pos] = t;
        g_sorted_w[pos]   = g_topk_w[2 * t + k];
    }
}

// ---------------- GEMM tiling constants --------------------------------------
// fp16: BK=16 halves/stage = 8 u32 per row; stride 12 u32 (48B) -> the 8
// ldmatrix row-addresses per 8x8 mat land at {0,48,96,16,64,112,32,80} mod 128B:
// all distinct banks, conflict-free.
constexpr int BM = 128;
constexpr int BN = 64;
constexpr int BK = 16;
constexpr int AST = 12;     // u32 stride per row (8 used + 4 pad)

// ---------------- kernel 4: gate/up GEMM + fused SwiGLU ----------------------
// grid: (32 m-tiles, 22 n-tiles over I, 16 experts), 256 threads
__global__ __launch_bounds__(256, 2)
void g1_kernel(const float* __restrict__ hs, const float* __restrict__ ws) {
    __shared__ uint32_t As[2][BM * AST];
    __shared__ uint32_t Bg[2][BN * AST];
    __shared__ uint32_t Bu[2][BN * AST];
    __shared__ int      stok[BM];

    const int e    = blockIdx.z;
    const int off  = g_offsets[e];
    const int rows = g_offsets[e + 1] - off;
    const int m0   = blockIdx.x * BM;
    if (m0 >= rows) return;
    const int n0  = blockIdx.y * BN;
    const int tid = threadIdx.x;

    if (tid < BM) {
        int am = m0 + tid;
        stok[tid] = (am < rows) ? g_sorted_tok[off + am] : -1;
    }
    __syncthreads();

    const float* wg = ws + (size_t)e * TI_ * H_ + (size_t)n0 * H_;
    const float* wu = ws + (size_t)e * TI_ * H_ + (size_t)(I_ + n0) * H_;

    // A: 128 rows x 4 quads (16 floats/row) = 512 float4, 2 per thread
    const int ar0 = (tid * 2) >> 2,     aq0 = (tid * 2) & 3;
    const int ar1 = (tid * 2 + 1) >> 2, aq1 = (tid * 2 + 1) & 3;
    // B: 64 rows x 4 quads = 256 float4, 1 per thread (each of Bg, Bu)
    const int brw = tid >> 2,           bq  = tid & 3;
    const int tok0 = stok[ar0];
    const int tok1 = stok[ar1];
    const float* ap0 = hs + (size_t)(tok0 < 0 ? 0 : tok0) * H_ + aq0 * 4;
    const float* ap1 = hs + (size_t)(tok1 < 0 ? 0 : tok1) * H_ + aq1 * 4;
    const float* bgp = wg + (size_t)brw * H_ + bq * 4;
    const float* bup = wu + (size_t)brw * H_ + bq * 4;

    float4 va0, va1, vbg, vbu;
    const float4 z4 = make_float4(0.f, 0.f, 0.f, 0.f);

    float accG[2][4][4] = {};
    float accU[2][4][4] = {};

    const int lane = tid & 31, warp = tid >> 5;
    const int wm = (warp >> 1) * 32;   // 4 warps along M
    const int wn = (warp & 1) * 32;    // 2 warps along N
    const int grp = lane >> 2, tig = lane & 3;

    // ldmatrix shared-space base addresses + per-lane offsets
    const uint32_t sA0 = (uint32_t)__cvta_generic_to_shared(&As[0][0]);
    const uint32_t sA1 = (uint32_t)__cvta_generic_to_shared(&As[1][0]);
    const uint32_t sG0 = (uint32_t)__cvta_generic_to_shared(&Bg[0][0]);
    const uint32_t sG1 = (uint32_t)__cvta_generic_to_shared(&Bg[1][0]);
    const uint32_t sU0 = (uint32_t)__cvta_generic_to_shared(&Bu[0][0]);
    const uint32_t sU1 = (uint32_t)__cvta_generic_to_shared(&Bu[1][0]);
    // A: lanes 0-15 -> rows wm+0..15 chunk0 (k0-7); lanes 16-31 -> same rows chunk1
    const uint32_t aOff = (uint32_t)((wm + (lane & 15)) * AST * 4 + (lane >> 4) * 16);
    // B: mat j = lane>>3: row = ((lane>>4)&1)*8 + (lane&7), chunk = (lane>>3)&1
    const uint32_t bOff = (uint32_t)((wn + ((lane >> 4) & 1) * 8 + (lane & 7)) * AST * 4
                                     + ((lane >> 3) & 1) * 16);

    auto fetch = [&](int kn) {
        va0 = (tok0 >= 0) ? *(const float4*)(ap0 + kn) : z4;
        va1 = (tok1 >= 0) ? *(const float4*)(ap1 + kn) : z4;
        vbg = *(const float4*)(bgp + kn);
        vbu = *(const float4*)(bup + kn);
    };
    auto stage = [&](int b) {
        uint32_t* p;
        p = &As[b][ar0 * AST + aq0 * 2]; p[0] = pack_h2(va0.x, va0.y); p[1] = pack_h2(va0.z, va0.w);
        p = &As[b][ar1 * AST + aq1 * 2]; p[0] = pack_h2(va1.x, va1.y); p[1] = pack_h2(va1.z, va1.w);
        p = &Bg[b][brw * AST + bq * 2];  p[0] = pack_h2(vbg.x, vbg.y); p[1] = pack_h2(vbg.z, vbg.w);
        p = &Bu[b][brw * AST + bq * 2];  p[0] = pack_h2(vbu.x, vbu.y); p[1] = pack_h2(vbu.z, vbu.w);
    };
    auto compute = [&](uint32_t sA, uint32_t sG, uint32_t sU) {
        uint32_t af[2][4], gf[2][4], uf[2][4];
#pragma unroll
        for (int mm = 0; mm < 2; mm++)
            ldsm_x4(af[mm], sA + aOff + (uint32_t)(mm * 16 * AST * 4));
#pragma unroll
        for (int p = 0; p < 2; p++) {
            ldsm_x4(gf[p], sG + bOff + (uint32_t)(p * 16 * AST * 4));
            ldsm_x4(uf[p], sU + bOff + (uint32_t)(p * 16 * AST * 4));
        }
#pragma unroll
        for (int nn = 0; nn < 4; nn++) {
            uint32_t bg2[2] = { gf[nn >> 1][(nn & 1) * 2], gf[nn >> 1][(nn & 1) * 2 + 1] };
            uint32_t bu2[2] = { uf[nn >> 1][(nn & 1) * 2], uf[nn >> 1][(nn & 1) * 2 + 1] };
#pragma unroll
            for (int mm = 0; mm < 2; mm++) {
                mma_f16(accG[mm][nn], af[mm], bg2);
                mma_f16(accU[mm][nn], af[mm], bu2);
            }
        }
    };

    // prologue
    fetch(0);
    stage(0);
    __syncthreads();

    constexpr int NS = H_ / BK;   // 128 (even)
#pragma unroll 1
    for (int s = 0; s < NS; s += 2) {
        fetch((s + 1) * BK);
        compute(sA0, sG0, sU0);
        stage(1);
        __syncthreads();
        const bool more = (s + 2) < NS;
        if (more) fetch((s + 2) * BK);
        compute(sA1, sG1, sU1);
        if (more) {
            stage(0);
            __syncthreads();
        }
    }

    // fused SwiGLU epilogue -> hbuf
#pragma unroll
    for (int mm = 0; mm < 2; mm++) {
#pragma unroll
        for (int nn = 0; nn < 4; nn++) {
            const int r = wm + mm * 16 + grp;
            const int c = n0 + wn + nn * 8 + tig * 2;
            const float* G = accG[mm][nn];
            const float* U = accU[mm][nn];
            if (m0 + r < rows) {
                size_t b = (size_t)(off + m0 + r) * I_ + c;
                g_hbuf[b]     = silu_f(G[0]) * U[0];
                g_hbuf[b + 1] = silu_f(G[1]) * U[1];
            }
            if (m0 + r + 8 < rows) {
                size_t b = (size_t)(off + m0 + r + 8) * I_ + c;
                g_hbuf[b]     = silu_f(G[2]) * U[2];
                g_hbuf[b + 1] = silu_f(G[3]) * U[3];
            }
        }
    }
}

// ---------------- kernel 5: down GEMM + weighted scatter-add -----------------
// grid: (32 m-tiles, 32 n-tiles over H, 16 experts), 256 threads
__global__ __launch_bounds__(256, 2)
void g2_kernel(const float* __restrict__ w2s, float* __restrict__ out) {
    __shared__ uint32_t As[2][BM * AST];
    __shared__ uint32_t Bs[2][BN * AST];
    __shared__ int      stok[BM];
    __shared__ float    sw[BM];

    const int e    = blockIdx.z;
    const int off  = g_offsets[e];
    const int rows = g_offsets[e + 1] - off;
    const int m0   = blockIdx.x * BM;
    if (m0 >= rows) return;
    const int n0  = blockIdx.y * BN;
    const int tid = threadIdx.x;

    if (tid < BM) {
        int am = m0 + tid;
        bool v = (am < rows);
        stok[tid] = v ? g_sorted_tok[off + am] : -1;
        sw[tid]   = v ? g_sorted_w[off + am]   : 0.0f;
    }
    __syncthreads();

    const float* wb = w2s + (size_t)e * H_ * I_ + (size_t)n0 * I_;

    const int ar0 = (tid * 2) >> 2,     aq0 = (tid * 2) & 3;
    const int ar1 = (tid * 2 + 1) >> 2, aq1 = (tid * 2 + 1) & 3;
    const int brw = tid >> 2,           bq  = tid & 3;
    const bool v0 = (m0 + ar0) < rows;
    const bool v1 = (m0 + ar1) < rows;
    const float* ap0 = g_hbuf + (size_t)(off + (v0 ? m0 + ar0 : 0)) * I_ + aq0 * 4;
    const float* ap1 = g_hbuf + (size_t)(off + (v1 ? m0 + ar1 : 0)) * I_ + aq1 * 4;
    const float* bp  = wb + (size_t)brw * I_ + bq * 4;

    float4 va0, va1, vb;
    const float4 z4 = make_float4(0.f, 0.f, 0.f, 0.f);

    float acc[2][4][4] = {};

    const int lane = tid & 31, warp = tid >> 5;
    const int wm = (warp >> 1) * 32;
    const int wn = (warp & 1) * 32;
    const int grp = lane >> 2, tig = lane & 3;

    const uint32_t sA0 = (uint32_t)__cvta_generic_to_shared(&As[0][0]);
    const uint32_t sA1 = (uint32_t)__cvta_generic_to_shared(&As[1][0]);
    const uint32_t sB0 = (uint32_t)__cvta_generic_to_shared(&Bs[0][0]);
    const uint32_t sB1 = (uint32_t)__cvta_generic_to_shared(&Bs[1][0]);
    const uint32_t aOff = (uint32_t)((wm + (lane & 15)) * AST * 4 + (lane >> 4) * 16);
    const uint32_t bOff = (uint32_t)((wn + ((lane >> 4) & 1) * 8 + (lane & 7)) * AST * 4
                                     + ((lane >> 3) & 1) * 16);

    auto fetch = [&](int kn) {
        va0 = v0 ? *(const float4*)(ap0 + kn) : z4;
        va1 = v1 ? *(const float4*)(ap1 + kn) : z4;
        vb  = *(const float4*)(bp + kn);
    };
    auto stage = [&](int b) {
        uint32_t* p;
        p = &As[b][ar0 * AST + aq0 * 2]; p[0] = pack_h2(va0.x, va0.y); p[1] = pack_h2(va0.z, va0.w);
        p = &As[b][ar1 * AST + aq1 * 2]; p[0] = pack_h2(va1.x, va1.y); p[1] = pack_h2(va1.z, va1.w);
        p = &Bs[b][brw * AST + bq * 2];  p[0] = pack_h2(vb.x, vb.y);   p[1] = pack_h2(vb.z, vb.w);
    };
    auto compute = [&](uint32_t sA, uint32_t sB) {
        uint32_t af[2][4], bf[2][4];
#pragma unroll
        for (int mm = 0; mm < 2; mm++)
            ldsm_x4(af[mm], sA + aOff + (uint32_t)(mm * 16 * AST * 4));
#pragma unroll
        for (int p = 0; p < 2; p++)
            ldsm_x4(bf[p], sB + bOff + (uint32_t)(p * 16 * AST * 4));
#pragma unroll
        for (int nn = 0; nn < 4; nn++) {
            uint32_t b2[2] = { bf[nn >> 1][(nn & 1) * 2], bf[nn >> 1][(nn & 1) * 2 + 1] };
#pragma unroll
            for (int mm = 0; mm < 2; mm++) {
                mma_f16(acc[mm][nn], af[mm], b2);
            }
        }
    };

    fetch(0);
    stage(0);
    __syncthreads();

    constexpr int NS = I_ / BK;   // 88 (even)
#pragma unroll 1
    for (int s = 0; s < NS; s += 2) {
        fetch((s + 1) * BK);
        compute(sA0, sB0);
        stage(1);
        __syncthreads();
        const bool more = (s + 2) < NS;
        if (more) fetch((s + 2) * BK);
        compute(sA1, sB1);
        if (more) {
            stage(0);
            __syncthreads();
        }
    }

    // weighted scatter-add epilogue (exactly 2 commutative adds per out element)
#pragma unroll
    for (int mm = 0; mm < 2; mm++) {
#pragma unroll
        for (int nn = 0; nn < 4; nn++) {
            const int r = wm + mm * 16 + grp;
            const int c = n0 + wn + nn * 8 + tig * 2;
            const float* D = acc[mm][nn];
            int t1 = stok[r];
            if (t1 >= 0) {
                float w = sw[r];
                atomicAdd(&out[(size_t)t1 * H_ + c],     w * D[0]);
                atomicAdd(&out[(size_t)t1 * H_ + c + 1], w * D[1]);
            }
            int t2 = stok[r + 8];
            if (t2 >= 0) {
                float w = sw[r + 8];
                atomicAdd(&out[(size_t)t2 * H_ + c],     w * D[2]);
                atomicAdd(&out[(size_t)t2 * H_ + c + 1], w * D[3]);
            }
        }
    }
}

// ---------------- launch -----------------------------------------------------
extern "C" void kernel_launch(void* const* d_in, const int* in_sizes, int n_in,
                              void* d_out, int out_size) {
    const float* hs  = (const float*)d_in[0];   // [T, H]
    const float* gw  = (const float*)d_in[1];   // [E, H]
    const float* ws  = (const float*)d_in[2];   // [E, 2I, H]
    const float* w2s = (const float*)d_in[3];   // [E, H, I]
    float* out = (float*)d_out;                 // [T, H]
    (void)in_sizes; (void)n_in; (void)out_size; // top_k fixed at 2

    init_kernel<<<2048, 256>>>(out);
    router_kernel<<<T_, 128>>>(hs, gw);
    scan_kernel<<<1, 32>>>();
    scatter_kernel<<<(T_ + 255) / 256, 256>>>();
    {
        dim3 grid(32, I_ / BN, E_);   // 32 x 22 x 16
        g1_kernel<<<grid, 256>>>(hs, ws);
    }
    {
        dim3 grid(32, H_ / BN, E_);   // 32 x 32 x 16
        g2_kernel<<<grid, 256>>>(w2s, out);
    }
}

// round 14
// speedup vs baseline: 1.7657x; 1.0070x over previous
#include <cuda_runtime.h>
#include <cuda_fp16.h>
#include <cstdint>

#define T_  4096
#define H_  2048
#define I_  1408
#define E_  16
#define TI_ 2816            // 2*I
#define SLOTS (T_*2)        // 8192 (token, expert) pairs
#define MAXMT 80            // max total m-tiles: 8192/128 + 16

// ---------------- scratch (device globals: no allocation allowed) -----------
__device__ int    g_topk_ids[SLOTS];
__device__ float  g_topk_w[SLOTS];
__device__ int    g_counts[E_];
__device__ int    g_offsets[E_ + 1];
__device__ int    g_cursor[E_];
__device__ int    g_sorted_tok[SLOTS];
__device__ float  g_sorted_w[SLOTS];
__device__ float  g_hbuf[(size_t)SLOTS * I_];   // 46 MB intermediate (silu(g)*u)
// persistent-kernel work queue state
__device__ int    g_mt_e[MAXMT];    // m-tile -> expert
__device__ int    g_mt_m0[MAXMT];   // m-tile -> row offset within expert
__device__ int    g_done[MAXMT];    // per (e,mt): completed g1 n-tiles (target 22)
__device__ int    g_next;           // global work cursor
__device__ int    g_nw1;            // #g1 items = nmt*22
__device__ int    g_nwtot;          // nmt*22 + nmt*32

// ---------------- helpers ---------------------------------------------------
__device__ __forceinline__ void mma_f16(float d[4], const uint32_t a[4], const uint32_t b[2]) {
    asm volatile(
        "mma.sync.aligned.m16n8k16.row.col.f32.f16.f16.f32 "
        "{%0,%1,%2,%3}, {%4,%5,%6,%7}, {%8,%9}, {%0,%1,%2,%3};\n"
        : "+f"(d[0]), "+f"(d[1]), "+f"(d[2]), "+f"(d[3])
        : "r"(a[0]), "r"(a[1]), "r"(a[2]), "r"(a[3]), "r"(b[0]), "r"(b[1]));
}

__device__ __forceinline__ void ldsm_x4(uint32_t r[4], uint32_t saddr) {
    asm volatile("ldmatrix.sync.aligned.m8n8.x4.shared.b16 {%0,%1,%2,%3}, [%4];"
                 : "=r"(r[0]), "=r"(r[1]), "=r"(r[2]), "=r"(r[3]) : "r"(saddr));
}

__device__ __forceinline__ uint32_t pack_h2(float lo, float hi) {
    __half2 h = __floats2half2_rn(lo, hi);
    return *(uint32_t*)&h;
}

__device__ __forceinline__ float silu_f(float x) {
    return x / (1.0f + expf(-x));
}

// ---------------- kernel 1: router (zeroes its out row; 1 block/token) ------
__global__ void router_kernel(const float* __restrict__ hs, const float* __restrict__ gw,
                              float* __restrict__ out) {
    __shared__ float sh[H_];
    __shared__ float slog[E_];
    const int t = blockIdx.x;
    const int tid = threadIdx.x;

    // zero this token's output row (replaces init_kernel; out poisoned 0xAA)
    float4* orow = (float4*)(out + (size_t)t * H_);
#pragma unroll
    for (int i = 0; i < 4; i++)
        orow[tid + i * 128] = make_float4(0.f, 0.f, 0.f, 0.f);

    const float* hr = hs + (size_t)t * H_;
    for (int i = tid; i < H_; i += 128) sh[i] = hr[i];
    __syncthreads();

    const int e = tid >> 3;   // 16 experts, 8 threads each
    const int r = tid & 7;
    const float* gr = gw + (size_t)e * H_;
    float s = 0.0f;
    for (int k = r; k < H_; k += 8) s += sh[k] * gr[k];
    s += __shfl_xor_sync(0xffffffffu, s, 4);
    s += __shfl_xor_sync(0xffffffffu, s, 2);
    s += __shfl_xor_sync(0xffffffffu, s, 1);
    if (r == 0) slog[e] = s;
    __syncthreads();

    if (tid == 0) {
        int i0 = 0; float l0 = slog[0];
        for (int i = 1; i < E_; i++) if (slog[i] > l0) { l0 = slog[i]; i0 = i; }
        int i1 = -1; float l1 = -1e30f;
        for (int i = 0; i < E_; i++) if (i != i0 && slog[i] > l1) { l1 = slog[i]; i1 = i; }
        float p1 = expf(l1 - l0);
        float inv = 1.0f / (1.0f + p1);
        g_topk_ids[2 * t]     = i0;
        g_topk_ids[2 * t + 1] = i1;
        g_topk_w[2 * t]     = inv;
        g_topk_w[2 * t + 1] = p1 * inv;
        atomicAdd(&g_counts[i0], 1);
        atomicAdd(&g_counts[i1], 1);
    }
}

// ---------------- kernel 2: scan + dense tile table + queue reset ------------
__global__ void scan_kernel() {
    if (threadIdx.x == 0) {
        int acc = 0;
        g_offsets[0] = 0;
        for (int e = 0; e < E_; e++) {
            g_cursor[e] = acc;
            acc += g_counts[e];
            g_offsets[e + 1] = acc;
        }
        int nmt = 0;
        for (int e = 0; e < E_; e++) {
            int rows = g_offsets[e + 1] - g_offsets[e];
            for (int m0 = 0; m0 < rows; m0 += 128) {
                g_mt_e[nmt]  = e;
                g_mt_m0[nmt] = m0;
                nmt++;
            }
        }
        g_nw1   = nmt * 22;             // g1 items (I/64 n-tiles)
        g_nwtot = nmt * 22 + nmt * 32;  // + g2 items (H/64 n-tiles)
        g_next  = 0;
        for (int i = 0; i < MAXMT; i++) g_done[i] = 0;
    }
}

// ---------------- kernel 3: scatter (also re-zeros counts for next replay) ---
__global__ void scatter_kernel() {
    int t = blockIdx.x * blockDim.x + threadIdx.x;
    if (t < E_) g_counts[t] = 0;   // consumed by scan already; reset for replay
    if (t >= T_) return;
#pragma unroll
    for (int k = 0; k < 2; k++) {
        int e = g_topk_ids[2 * t + k];
        int pos = atomicAdd(&g_cursor[e], 1);
        g_sorted_tok[pos] = t;
        g_sorted_w[pos]   = g_topk_w[2 * t + k];
    }
}

// ---------------- GEMM tiling constants --------------------------------------
constexpr int BM = 128;
constexpr int BN = 64;
constexpr int BK = 16;
constexpr int AST = 12;     // u32 stride per row (8 used + 4 pad) — ldmatrix conflict-free

// ---------------- fused persistent MoE kernel --------------------------------
// Shared pool (g1 view: As[2] + Bg[2] + Bu[2]; g2 view: As[2] + Bs[2]).
struct SmemPool {
    uint32_t As[2][BM * AST];   // 12288 B
    uint32_t Bx[2][BN * AST];   //  6144 B (g1: Bg, g2: Bs)
    uint32_t By[2][BN * AST];   //  6144 B (g1: Bu, g2: unused)
    int      stok[BM];
    float    sw[BM];
    int      item;
};

__device__ __forceinline__ void g1_tile(SmemPool& sm, const float* __restrict__ hs,
                                        const float* __restrict__ ws,
                                        int e, int m0, int ny, int mt) {
    const int off  = g_offsets[e];
    const int rows = g_offsets[e + 1] - off;
    const int n0   = ny * BN;
    const int tid  = threadIdx.x;

    if (tid < BM) {
        int am = m0 + tid;
        sm.stok[tid] = (am < rows) ? g_sorted_tok[off + am] : -1;
    }
    __syncthreads();

    const float* wg = ws + (size_t)e * TI_ * H_ + (size_t)n0 * H_;
    const float* wu = ws + (size_t)e * TI_ * H_ + (size_t)(I_ + n0) * H_;

    const int ar0 = (tid * 2) >> 2,     aq0 = (tid * 2) & 3;
    const int ar1 = (tid * 2 + 1) >> 2, aq1 = (tid * 2 + 1) & 3;
    const int brw = tid >> 2,           bq  = tid & 3;
    const int tok0 = sm.stok[ar0];
    const int tok1 = sm.stok[ar1];
    const float* ap0 = hs + (size_t)(tok0 < 0 ? 0 : tok0) * H_ + aq0 * 4;
    const float* ap1 = hs + (size_t)(tok1 < 0 ? 0 : tok1) * H_ + aq1 * 4;
    const float* bgp = wg + (size_t)brw * H_ + bq * 4;
    const float* bup = wu + (size_t)brw * H_ + bq * 4;

    float4 va0, va1, vbg, vbu;
    const float4 z4 = make_float4(0.f, 0.f, 0.f, 0.f);

    float accG[2][4][4] = {};
    float accU[2][4][4] = {};

    const int lane = tid & 31, warp = tid >> 5;
    const int wm = (warp >> 1) * 32;
    const int wn = (warp & 1) * 32;
    const int grp = lane >> 2, tig = lane & 3;

    const uint32_t sA0 = (uint32_t)__cvta_generic_to_shared(&sm.As[0][0]);
    const uint32_t sA1 = (uint32_t)__cvta_generic_to_shared(&sm.As[1][0]);
    const uint32_t sG0 = (uint32_t)__cvta_generic_to_shared(&sm.Bx[0][0]);
    const uint32_t sG1 = (uint32_t)__cvta_generic_to_shared(&sm.Bx[1][0]);
    const uint32_t sU0 = (uint32_t)__cvta_generic_to_shared(&sm.By[0][0]);
    const uint32_t sU1 = (uint32_t)__cvta_generic_to_shared(&sm.By[1][0]);
    const uint32_t aOff = (uint32_t)((wm + (lane & 15)) * AST * 4 + (lane >> 4) * 16);
    const uint32_t bOff = (uint32_t)((wn + ((lane >> 4) & 1) * 8 + (lane & 7)) * AST * 4
                                     + ((lane >> 3) & 1) * 16);

    auto fetch = [&](int kn) {
        va0 = (tok0 >= 0) ? *(const float4*)(ap0 + kn) : z4;
        va1 = (tok1 >= 0) ? *(const float4*)(ap1 + kn) : z4;
        vbg = *(const float4*)(bgp + kn);
        vbu = *(const float4*)(bup + kn);
    };
    auto stage = [&](int b) {
        uint32_t* p;
        p = &sm.As[b][ar0 * AST + aq0 * 2]; p[0] = pack_h2(va0.x, va0.y); p[1] = pack_h2(va0.z, va0.w);
        p = &sm.As[b][ar1 * AST + aq1 * 2]; p[0] = pack_h2(va1.x, va1.y); p[1] = pack_h2(va1.z, va1.w);
        p = &sm.Bx[b][brw * AST + bq * 2];  p[0] = pack_h2(vbg.x, vbg.y); p[1] = pack_h2(vbg.z, vbg.w);
        p = &sm.By[b][brw * AST + bq * 2];  p[0] = pack_h2(vbu.x, vbu.y); p[1] = pack_h2(vbu.z, vbu.w);
    };
    auto compute = [&](uint32_t sA, uint32_t sG, uint32_t sU) {
        uint32_t af[2][4], gf[2][4], uf[2][4];
#pragma unroll
        for (int mm = 0; mm < 2; mm++)
            ldsm_x4(af[mm], sA + aOff + (uint32_t)(mm * 16 * AST * 4));
#pragma unroll
        for (int p = 0; p < 2; p++) {
            ldsm_x4(gf[p], sG + bOff + (uint32_t)(p * 16 * AST * 4));
            ldsm_x4(uf[p], sU + bOff + (uint32_t)(p * 16 * AST * 4));
        }
#pragma unroll
        for (int nn = 0; nn < 4; nn++) {
            uint32_t bg2[2] = { gf[nn >> 1][(nn & 1) * 2], gf[nn >> 1][(nn & 1) * 2 + 1] };
            uint32_t bu2[2] = { uf[nn >> 1][(nn & 1) * 2], uf[nn >> 1][(nn & 1) * 2 + 1] };
#pragma unroll
            for (int mm = 0; mm < 2; mm++) {
                mma_f16(accG[mm][nn], af[mm], bg2);
                mma_f16(accU[mm][nn], af[mm], bu2);
            }
        }
    };

    fetch(0);
    stage(0);
    __syncthreads();

    constexpr int NS = H_ / BK;   // 128
#pragma unroll 1
    for (int s = 0; s < NS; s += 2) {
        fetch((s + 1) * BK);
        compute(sA0, sG0, sU0);
        stage(1);
        __syncthreads();
        const bool more = (s + 2) < NS;
        if (more) fetch((s + 2) * BK);
        compute(sA1, sG1, sU1);
        if (more) {
            stage(0);
            __syncthreads();
        }
    }

    // fused SwiGLU epilogue -> hbuf
#pragma unroll
    for (int mm = 0; mm < 2; mm++) {
#pragma unroll
        for (int nn = 0; nn < 4; nn++) {
            const int r = wm + mm * 16 + grp;
            const int c = n0 + wn + nn * 8 + tig * 2;
            const float* G = accG[mm][nn];
            const float* U = accU[mm][nn];
            if (m0 + r < rows) {
                size_t b = (size_t)(off + m0 + r) * I_ + c;
                g_hbuf[b]     = silu_f(G[0]) * U[0];
                g_hbuf[b + 1] = silu_f(G[1]) * U[1];
            }
            if (m0 + r + 8 < rows) {
                size_t b = (size_t)(off + m0 + r + 8) * I_ + c;
                g_hbuf[b]     = silu_f(G[2]) * U[2];
                g_hbuf[b + 1] = silu_f(G[3]) * U[3];
            }
        }
    }

    // publish: all hbuf writes for this (e,mt,ny) visible, then bump counter
    __syncthreads();
    __threadfence();
    if (tid == 0) atomicAdd(&g_done[mt], 1);
}

__device__ __forceinline__ void g2_tile(SmemPool& sm, const float* __restrict__ w2s,
                                        float* __restrict__ out,
                                        int e, int m0, int ny, int mt) {
    const int tid = threadIdx.x;

    // acquire: wait for all 22 g1 producer tiles of this (e,mt)
    if (tid == 0) {
        while (atomicAdd(&g_done[mt], 0) < 22) __nanosleep(200);
    }
    __syncthreads();
    __threadfence();

    const int off  = g_offsets[e];
    const int rows = g_offsets[e + 1] - off;
    const int n0   = ny * BN;

    if (tid < BM) {
        int am = m0 + tid;
        bool v = (am < rows);
        sm.stok[tid] = v ? g_sorted_tok[off + am] : -1;
        sm.sw[tid]   = v ? g_sorted_w[off + am]   : 0.0f;
    }
    __syncthreads();

    const float* wb = w2s + (size_t)e * H_ * I_ + (size_t)n0 * I_;

    const int ar0 = (tid * 2) >> 2,     aq0 = (tid * 2) & 3;
    const int ar1 = (tid * 2 + 1) >> 2, aq1 = (tid * 2 + 1) & 3;
    const int brw = tid >> 2,           bq  = tid & 3;
    const bool v0 = (m0 + ar0) < rows;
    const bool v1 = (m0 + ar1) < rows;
    const float* ap0 = g_hbuf + (size_t)(off + (v0 ? m0 + ar0 : 0)) * I_ + aq0 * 4;
    const float* ap1 = g_hbuf + (size_t)(off + (v1 ? m0 + ar1 : 0)) * I_ + aq1 * 4;
    const float* bp  = wb + (size_t)brw * I_ + bq * 4;

    float4 va0, va1, vb;
    const float4 z4 = make_float4(0.f, 0.f, 0.f, 0.f);

    float acc[2][4][4] = {};

    const int lane = tid & 31, warp = tid >> 5;
    const int wm = (warp >> 1) * 32;
    const int wn = (warp & 1) * 32;
    const int grp = lane >> 2, tig = lane & 3;

    const uint32_t sA0 = (uint32_t)__cvta_generic_to_shared(&sm.As[0][0]);
    const uint32_t sA1 = (uint32_t)__cvta_generic_to_shared(&sm.As[1][0]);
    const uint32_t sB0 = (uint32_t)__cvta_generic_to_shared(&sm.Bx[0][0]);
    const uint32_t sB1 = (uint32_t)__cvta_generic_to_shared(&sm.Bx[1][0]);
    const uint32_t aOff = (uint32_t)((wm + (lane & 15)) * AST * 4 + (lane >> 4) * 16);
    const uint32_t bOff = (uint32_t)((wn + ((lane >> 4) & 1) * 8 + (lane & 7)) * AST * 4
                                     + ((lane >> 3) & 1) * 16);

    auto fetch = [&](int kn) {
        va0 = v0 ? *(const float4*)(ap0 + kn) : z4;
        va1 = v1 ? *(const float4*)(ap1 + kn) : z4;
        vb  = *(const float4*)(bp + kn);
    };
    auto stage = [&](int b) {
        uint32_t* p;
        p = &sm.As[b][ar0 * AST + aq0 * 2]; p[0] = pack_h2(va0.x, va0.y); p[1] = pack_h2(va0.z, va0.w);
        p = &sm.As[b][ar1 * AST + aq1 * 2]; p[0] = pack_h2(va1.x, va1.y); p[1] = pack_h2(va1.z, va1.w);
        p = &sm.Bx[b][brw * AST + bq * 2];  p[0] = pack_h2(vb.x, vb.y);   p[1] = pack_h2(vb.z, vb.w);
    };
    auto compute = [&](uint32_t sA, uint32_t sB) {
        uint32_t af[2][4], bf[2][4];
#pragma unroll
        for (int mm = 0; mm < 2; mm++)
            ldsm_x4(af[mm], sA + aOff + (uint32_t)(mm * 16 * AST * 4));
#pragma unroll
        for (int p = 0; p < 2; p++)
            ldsm_x4(bf[p], sB + bOff + (uint32_t)(p * 16 * AST * 4));
#pragma unroll
        for (int nn = 0; nn < 4; nn++) {
            uint32_t b2[2] = { bf[nn >> 1][(nn & 1) * 2], bf[nn >> 1][(nn & 1) * 2 + 1] };
#pragma unroll
            for (int mm = 0; mm < 2; mm++) {
                mma_f16(acc[mm][nn], af[mm], b2);
            }
        }
    };

    fetch(0);
    stage(0);
    __syncthreads();

    constexpr int NS = I_ / BK;   // 88
#pragma unroll 1
    for (int s = 0; s < NS; s += 2) {
        fetch((s + 1) * BK);
        compute(sA0, sB0);
        stage(1);
        __syncthreads();
        const bool more = (s + 2) < NS;
        if (more) fetch((s + 2) * BK);
        compute(sA1, sB1);
        if (more) {
            stage(0);
            __syncthreads();
        }
    }

    // weighted scatter-add epilogue
#pragma unroll
    for (int mm = 0; mm < 2; mm++) {
#pragma unroll
        for (int nn = 0; nn < 4; nn++) {
            const int r = wm + mm * 16 + grp;
            const int c = n0 + wn + nn * 8 + tig * 2;
            const float* D = acc[mm][nn];
            int t1 = sm.stok[r];
            if (t1 >= 0) {
                float w = sm.sw[r];
                atomicAdd(&out[(size_t)t1 * H_ + c],     w * D[0]);
                atomicAdd(&out[(size_t)t1 * H_ + c + 1], w * D[1]);
            }
            int t2 = sm.stok[r + 8];
            if (t2 >= 0) {
                float w = sm.sw[r + 8];
                atomicAdd(&out[(size_t)t2 * H_ + c],     w * D[2]);
                atomicAdd(&out[(size_t)t2 * H_ + c + 1], w * D[3]);
            }
        }
    }
    __syncthreads();   // protect smem reuse before next claimed item
}

__global__ __launch_bounds__(256, 2)
void moe_kernel(const float* __restrict__ hs, const float* __restrict__ ws,
                const float* __restrict__ w2s, float* __restrict__ out) {
    __shared__ SmemPool sm;
    const int tid = threadIdx.x;
    const int nw1   = g_nw1;
    const int nwtot = g_nwtot;

    for (;;) {
        if (tid == 0) sm.item = atomicAdd(&g_next, 1);
        __syncthreads();
        const int i = sm.item;
        if (i >= nwtot) return;
        if (i < nw1) {
            const int mt = i / 22, ny = i % 22;
            g1_tile(sm, hs, ws, g_mt_e[mt], g_mt_m0[mt], ny, mt);
        } else {
            const int j = i - nw1;
            const int mt = j / 32, ny = j % 32;
            g2_tile(sm, w2s, out, g_mt_e[mt], g_mt_m0[mt], ny, mt);
        }
    }
}

// ---------------- launch -----------------------------------------------------
extern "C" void kernel_launch(void* const* d_in, const int* in_sizes, int n_in,
                              void* d_out, int out_size) {
    const float* hs  = (const float*)d_in[0];   // [T, H]
    const float* gw  = (const float*)d_in[1];   // [E, H]
    const float* ws  = (const float*)d_in[2];   // [E, 2I, H]
    const float* w2s = (const float*)d_in[3];   // [E, H, I]
    float* out = (float*)d_out;                 // [T, H]
    (void)in_sizes; (void)n_in; (void)out_size; // top_k fixed at 2

    router_kernel<<<T_, 128>>>(hs, gw, out);
    scan_kernel<<<1, 32>>>();
    scatter_kernel<<<(T_ + 255) / 256, 256>>>();
    moe_kernel<<<296, 256>>>(hs, ws, w2s, out);   // persistent: 2 CTAs x 148 SMs
}

// round 16
// speedup vs baseline: 2.1474x; 1.2162x over previous
#include <cuda_runtime.h>
#include <cuda_fp16.h>
#include <cstdint>

#define T_  4096
#define H_  2048
#define I_  1408
#define E_  16
#define TI_ 2816            // 2*I
#define SLOTS (T_*2)        // 8192 (token, expert) pairs
#define MAXMT 80            // max total m-tiles: 8192/128 + 16

// ---------------- scratch (device globals: no allocation allowed) -----------
__device__ int    g_topk_ids[SLOTS];
__device__ float  g_topk_w[SLOTS];
__device__ int    g_counts[E_];
__device__ int    g_offsets[E_ + 1];
__device__ int    g_cursor[E_];
__device__ int    g_sorted_tok[SLOTS];
__device__ float  g_sorted_w[SLOTS];
// fp16 operand mirrors (converted every call); 16B-aligned for cp.async.cg
__device__ __align__(16) __half g_hs16[(size_t)T_ * H_];            // 16.8 MB
__device__ __align__(16) __half g_ws16[(size_t)E_ * TI_ * H_];      // 184 MB
__device__ __align__(16) __half g_w2s16[(size_t)E_ * H_ * I_];      // 92 MB
__device__ __align__(16) __half g_hbuf16[(size_t)SLOTS * I_];       // 23 MB
// persistent-kernel work queue state
__device__ int    g_mt_e[MAXMT];
__device__ int    g_mt_m0[MAXMT];
__device__ int    g_done[MAXMT];
__device__ int    g_next;
__device__ int    g_nw1;
__device__ int    g_nwtot;

// ---------------- helpers ---------------------------------------------------
__device__ __forceinline__ void mma_f16(float d[4], const uint32_t a[4], const uint32_t b[2]) {
    asm volatile(
        "mma.sync.aligned.m16n8k16.row.col.f32.f16.f16.f32 "
        "{%0,%1,%2,%3}, {%4,%5,%6,%7}, {%8,%9}, {%0,%1,%2,%3};\n"
        : "+f"(d[0]), "+f"(d[1]), "+f"(d[2]), "+f"(d[3])
        : "r"(a[0]), "r"(a[1]), "r"(a[2]), "r"(a[3]), "r"(b[0]), "r"(b[1]));
}

__device__ __forceinline__ void ldsm_x4(uint32_t r[4], uint32_t saddr) {
    asm volatile("ldmatrix.sync.aligned.m8n8.x4.shared.b16 {%0,%1,%2,%3}, [%4];"
                 : "=r"(r[0]), "=r"(r[1]), "=r"(r[2]), "=r"(r[3]) : "r"(saddr));
}

// 16B async copy; pred=false -> zero-fill (src not dereferenced)
__device__ __forceinline__ void cp_async16(uint32_t dst, const void* src, bool pred) {
    int sz = pred ? 16 : 0;
    asm volatile("cp.async.cg.shared.global [%0], [%1], 16, %2;"
                 :: "r"(dst), "l"(src), "r"(sz) : "memory");
}
#define CP_COMMIT() asm volatile("cp.async.commit_group;" ::: "memory")
#define CP_WAIT0()  asm volatile("cp.async.wait_group 0;" ::: "memory")

__device__ __forceinline__ float silu_f(float x) {
    return x / (1.0f + expf(-x));
}

// ---------------- kernel 0: fp32 -> fp16 operand conversion ------------------
__global__ void conv_kernel(const float* __restrict__ hs, const float* __restrict__ ws,
                            const float* __restrict__ w2s) {
    const size_t idx    = (size_t)blockIdx.x * blockDim.x + threadIdx.x;
    const size_t stride = (size_t)gridDim.x * blockDim.x;

    const size_t WSN  = (size_t)E_ * TI_ * H_ / 4;
    const size_t W2N  = (size_t)E_ * H_ * I_ / 4;
    const size_t HSN  = (size_t)T_ * H_ / 4;

    const float4* s;
    uint2* d;

    s = (const float4*)ws;  d = (uint2*)g_ws16;
    for (size_t i = idx; i < WSN; i += stride) {
        float4 v = s[i];
        __half2 h0 = __floats2half2_rn(v.x, v.y), h1 = __floats2half2_rn(v.z, v.w);
        d[i] = make_uint2(*(uint32_t*)&h0, *(uint32_t*)&h1);
    }
    s = (const float4*)w2s; d = (uint2*)g_w2s16;
    for (size_t i = idx; i < W2N; i += stride) {
        float4 v = s[i];
        __half2 h0 = __floats2half2_rn(v.x, v.y), h1 = __floats2half2_rn(v.z, v.w);
        d[i] = make_uint2(*(uint32_t*)&h0, *(uint32_t*)&h1);
    }
    s = (const float4*)hs;  d = (uint2*)g_hs16;
    for (size_t i = idx; i < HSN; i += stride) {
        float4 v = s[i];
        __half2 h0 = __floats2half2_rn(v.x, v.y), h1 = __floats2half2_rn(v.z, v.w);
        d[i] = make_uint2(*(uint32_t*)&h0, *(uint32_t*)&h1);
    }
}

// ---------------- kernel 1: router (zeroes its out row; 1 block/token) ------
__global__ void router_kernel(const float* __restrict__ hs, const float* __restrict__ gw,
                              float* __restrict__ out) {
    __shared__ float sh[H_];
    __shared__ float slog[E_];
    const int t = blockIdx.x;
    const int tid = threadIdx.x;

    float4* orow = (float4*)(out + (size_t)t * H_);
#pragma unroll
    for (int i = 0; i < 4; i++)
        orow[tid + i * 128] = make_float4(0.f, 0.f, 0.f, 0.f);

    const float* hr = hs + (size_t)t * H_;
    for (int i = tid; i < H_; i += 128) sh[i] = hr[i];
    __syncthreads();

    const int e = tid >> 3;
    const int r = tid & 7;
    const float* gr = gw + (size_t)e * H_;
    float s = 0.0f;
    for (int k = r; k < H_; k += 8) s += sh[k] * gr[k];
    s += __shfl_xor_sync(0xffffffffu, s, 4);
    s += __shfl_xor_sync(0xffffffffu, s, 2);
    s += __shfl_xor_sync(0xffffffffu, s, 1);
    if (r == 0) slog[e] = s;
    __syncthreads();

    if (tid == 0) {
        int i0 = 0; float l0 = slog[0];
        for (int i = 1; i < E_; i++) if (slog[i] > l0) { l0 = slog[i]; i0 = i; }
        int i1 = -1; float l1 = -1e30f;
        for (int i = 0; i < E_; i++) if (i != i0 && slog[i] > l1) { l1 = slog[i]; i1 = i; }
        float p1 = expf(l1 - l0);
        float inv = 1.0f / (1.0f + p1);
        g_topk_ids[2 * t]     = i0;
        g_topk_ids[2 * t + 1] = i1;
        g_topk_w[2 * t]     = inv;
        g_topk_w[2 * t + 1] = p1 * inv;
        atomicAdd(&g_counts[i0], 1);
        atomicAdd(&g_counts[i1], 1);
    }
}

// ---------------- kernel 2: scan + dense tile table + queue reset ------------
__global__ void scan_kernel() {
    if (threadIdx.x == 0) {
        int acc = 0;
        g_offsets[0] = 0;
        for (int e = 0; e < E_; e++) {
            g_cursor[e] = acc;
            acc += g_counts[e];
            g_offsets[e + 1] = acc;
        }
        int nmt = 0;
        for (int e = 0; e < E_; e++) {
            int rows = g_offsets[e + 1] - g_offsets[e];
            for (int m0 = 0; m0 < rows; m0 += 128) {
                g_mt_e[nmt]  = e;
                g_mt_m0[nmt] = m0;
                nmt++;
            }
        }
        g_nw1   = nmt * 22;
        g_nwtot = nmt * 22 + nmt * 32;
        g_next  = 0;
        for (int i = 0; i < MAXMT; i++) g_done[i] = 0;
    }
}

// ---------------- kernel 3: scatter ------------------------------------------
__global__ void scatter_kernel() {
    int t = blockIdx.x * blockDim.x + threadIdx.x;
    if (t < E_) g_counts[t] = 0;   // reset for next replay
    if (t >= T_) return;
#pragma unroll
    for (int k = 0; k < 2; k++) {
        int e = g_topk_ids[2 * t + k];
        int pos = atomicAdd(&g_cursor[e], 1);
        g_sorted_tok[pos] = t;
        g_sorted_w[pos]   = g_topk_w[2 * t + k];
    }
}

// ---------------- GEMM tiling constants --------------------------------------
constexpr int BM = 128;
constexpr int BN = 64;
constexpr int BK = 16;
constexpr int AST = 12;     // u32 stride per row (8 used + 4 pad) — ldmatrix conflict-free

struct SmemPool {
    uint32_t As[2][BM * AST];
    uint32_t Bx[2][BN * AST];   // g1: Bg, g2: Bs
    uint32_t By[2][BN * AST];   // g1: Bu
    int      stok[BM];
    float    sw[BM];
    int      item;
};

__device__ __forceinline__ void g1_tile(SmemPool& sm, int e, int m0, int ny, int mt) {
    const int off  = g_offsets[e];
    const int rows = g_offsets[e + 1] - off;
    const int n0   = ny * BN;
    const int tid  = threadIdx.x;

    if (tid < BM) {
        int am = m0 + tid;
        sm.stok[tid] = (am < rows) ? g_sorted_tok[off + am] : -1;
    }
    __syncthreads();

    // cp.async chunks: A = 256 x 16B (row=tid>>1, half=tid&1);
    // B: tid<128 -> Bg, tid>=128 -> Bu (128 chunks each)
    const int arow = tid >> 1, ahalf = tid & 1;
    const int tokA = sm.stok[arow];
    const bool aPred = (tokA >= 0);
    const __half* aSrc = g_hs16 + (size_t)(aPred ? tokA : 0) * H_ + ahalf * 8;
    const bool isBu = (tid >= 128);
    const int bi = tid & 127;
    const int brow = bi >> 1, bhalf = bi & 1;
    const __half* bSrc = g_ws16 + ((size_t)e * TI_ + (isBu ? I_ : 0) + n0 + brow) * H_ + bhalf * 8;

    uint32_t aDst[2], bDst[2];
    aDst[0] = (uint32_t)__cvta_generic_to_shared(&sm.As[0][arow * AST + ahalf * 4]);
    aDst[1] = (uint32_t)__cvta_generic_to_shared(&sm.As[1][arow * AST + ahalf * 4]);
    {
        uint32_t* b0 = isBu ? sm.By[0] : sm.Bx[0];
        uint32_t* b1 = isBu ? sm.By[1] : sm.Bx[1];
        bDst[0] = (uint32_t)__cvta_generic_to_shared(&b0[brow * AST + bhalf * 4]);
        bDst[1] = (uint32_t)__cvta_generic_to_shared(&b1[brow * AST + bhalf * 4]);
    }

    float accG[2][4][4] = {};
    float accU[2][4][4] = {};

    const int lane = tid & 31, warp = tid >> 5;
    const int wm = (warp >> 1) * 32;
    const int wn = (warp & 1) * 32;
    const int grp = lane >> 2, tig = lane & 3;

    uint32_t sA[2], sG[2], sU[2];
    sA[0] = (uint32_t)__cvta_generic_to_shared(&sm.As[0][0]);
    sA[1] = (uint32_t)__cvta_generic_to_shared(&sm.As[1][0]);
    sG[0] = (uint32_t)__cvta_generic_to_shared(&sm.Bx[0][0]);
    sG[1] = (uint32_t)__cvta_generic_to_shared(&sm.Bx[1][0]);
    sU[0] = (uint32_t)__cvta_generic_to_shared(&sm.By[0][0]);
    sU[1] = (uint32_t)__cvta_generic_to_shared(&sm.By[1][0]);
    const uint32_t aOff = (uint32_t)((wm + (lane & 15)) * AST * 4 + (lane >> 4) * 16);
    const uint32_t bOff = (uint32_t)((wn + ((lane >> 4) & 1) * 8 + (lane & 7)) * AST * 4
                                     + ((lane >> 3) & 1) * 16);

    auto cpstage = [&](int b, int k0) {
        cp_async16(aDst[b], aSrc + k0, aPred);
        cp_async16(bDst[b], bSrc + k0, true);
    };
    auto compute = [&](int b) {
        uint32_t af[2][4], gf[2][4], uf[2][4];
#pragma unroll
        for (int mm = 0; mm < 2; mm++)
            ldsm_x4(af[mm], sA[b] + aOff + (uint32_t)(mm * 16 * AST * 4));
#pragma unroll
        for (int p = 0; p < 2; p++) {
            ldsm_x4(gf[p], sG[b] + bOff + (uint32_t)(p * 16 * AST * 4));
            ldsm_x4(uf[p], sU[b] + bOff + (uint32_t)(p * 16 * AST * 4));
        }
#pragma unroll
        for (int nn = 0; nn < 4; nn++) {
            uint32_t bg2[2] = { gf[nn >> 1][(nn & 1) * 2], gf[nn >> 1][(nn & 1) * 2 + 1] };
            uint32_t bu2[2] = { uf[nn >> 1][(nn & 1) * 2], uf[nn >> 1][(nn & 1) * 2 + 1] };
#pragma unroll
            for (int mm = 0; mm < 2; mm++) {
                mma_f16(accG[mm][nn], af[mm], bg2);
                mma_f16(accU[mm][nn], af[mm], bu2);
            }
        }
    };

    cpstage(0, 0);
    CP_COMMIT();
    CP_WAIT0();
    __syncthreads();

    constexpr int NS = H_ / BK;   // 128 (even)
#pragma unroll 1
    for (int s = 0; s < NS; s += 2) {
        cpstage(1, (s + 1) * BK);       // s+1 < NS always (NS even)
        CP_COMMIT();
        compute(0);
        CP_WAIT0();
        __syncthreads();
        const bool more = (s + 2) < NS;
        if (more) {
            cpstage(0, (s + 2) * BK);
            CP_COMMIT();
        }
        compute(1);
        if (more) {
            CP_WAIT0();
            __syncthreads();
        }
    }

    // fused SwiGLU epilogue -> hbuf16 (same rounding as old stage-time convert)
#pragma unroll
    for (int mm = 0; mm < 2; mm++) {
#pragma unroll
        for (int nn = 0; nn < 4; nn++) {
            const int r = wm + mm * 16 + grp;
            const int c = n0 + wn + nn * 8 + tig * 2;
            const float* G = accG[mm][nn];
            const float* U = accU[mm][nn];
            if (m0 + r < rows) {
                size_t b = (size_t)(off + m0 + r) * I_ + c;
                *(__half2*)(g_hbuf16 + b) =
                    __floats2half2_rn(silu_f(G[0]) * U[0], silu_f(G[1]) * U[1]);
            }
            if (m0 + r + 8 < rows) {
                size_t b = (size_t)(off + m0 + r + 8) * I_ + c;
                *(__half2*)(g_hbuf16 + b) =
                    __floats2half2_rn(silu_f(G[2]) * U[2], silu_f(G[3]) * U[3]);
            }
        }
    }

    __syncthreads();
    __threadfence();
    if (tid == 0) atomicAdd(&g_done[mt], 1);
}

__device__ __forceinline__ void g2_tile(SmemPool& sm, float* __restrict__ out,
                                        int e, int m0, int ny, int mt) {
    const int tid = threadIdx.x;

    if (tid == 0) {
        while (atomicAdd(&g_done[mt], 0) < 22) __nanosleep(200);
    }
    __syncthreads();
    __threadfence();

    const int off  = g_offsets[e];
    const int rows = g_offsets[e + 1] - off;
    const int n0   = ny * BN;

    if (tid < BM) {
        int am = m0 + tid;
        bool v = (am < rows);
        sm.stok[tid] = v ? g_sorted_tok[off + am] : -1;
        sm.sw[tid]   = v ? g_sorted_w[off + am]   : 0.0f;
    }
    __syncthreads();

    const int arow = tid >> 1, ahalf = tid & 1;
    const bool aPred = (m0 + arow) < rows;
    const __half* aSrc = g_hbuf16 + (size_t)(off + (aPred ? m0 + arow : 0)) * I_ + ahalf * 8;
    const int brow = (tid & 127) >> 1, bhalf = tid & 1;
    const __half* bSrc = g_w2s16 + ((size_t)e * H_ + n0 + brow) * I_ + bhalf * 8;
    const bool doB = (tid < 128);

    uint32_t aDst[2], bDst[2];
    aDst[0] = (uint32_t)__cvta_generic_to_shared(&sm.As[0][arow * AST + ahalf * 4]);
    aDst[1] = (uint32_t)__cvta_generic_to_shared(&sm.As[1][arow * AST + ahalf * 4]);
    bDst[0] = (uint32_t)__cvta_generic_to_shared(&sm.Bx[0][brow * AST + bhalf * 4]);
    bDst[1] = (uint32_t)__cvta_generic_to_shared(&sm.Bx[1][brow * AST + bhalf * 4]);

    float acc[2][4][4] = {};

    const int lane = tid & 31, warp = tid >> 5;
    const int wm = (warp >> 1) * 32;
    const int wn = (warp & 1) * 32;
    const int grp = lane >> 2, tig = lane & 3;

    uint32_t sA[2], sB[2];
    sA[0] = (uint32_t)__cvta_generic_to_shared(&sm.As[0][0]);
    sA[1] = (uint32_t)__cvta_generic_to_shared(&sm.As[1][0]);
    sB[0] = (uint32_t)__cvta_generic_to_shared(&sm.Bx[0][0]);
    sB[1] = (uint32_t)__cvta_generic_to_shared(&sm.Bx[1][0]);
    const uint32_t aOff = (uint32_t)((wm + (lane & 15)) * AST * 4 + (lane >> 4) * 16);
    const uint32_t bOff = (uint32_t)((wn + ((lane >> 4) & 1) * 8 + (lane & 7)) * AST * 4
                                     + ((lane >> 3) & 1) * 16);

    auto cpstage = [&](int b, int k0) {
        cp_async16(aDst[b], aSrc + k0, aPred);
        if (doB) cp_async16(bDst[b], bSrc + k0, true);
    };
    auto compute = [&](int b) {
        uint32_t af[2][4], bf[2][4];
#pragma unroll
        for (int mm = 0; mm < 2; mm++)
            ldsm_x4(af[mm], sA[b] + aOff + (uint32_t)(mm * 16 * AST * 4));
#pragma unroll
        for (int p = 0; p < 2; p++)
            ldsm_x4(bf[p], sB[b] + bOff + (uint32_t)(p * 16 * AST * 4));
#pragma unroll
        for (int nn = 0; nn < 4; nn++) {
            uint32_t b2[2] = { bf[nn >> 1][(nn & 1) * 2], bf[nn >> 1][(nn & 1) * 2 + 1] };
#pragma unroll
            for (int mm = 0; mm < 2; mm++) {
                mma_f16(acc[mm][nn], af[mm], b2);
            }
        }
    };

    cpstage(0, 0);
    CP_COMMIT();
    CP_WAIT0();
    __syncthreads();

    constexpr int NS = I_ / BK;   // 88 (even)
#pragma unroll 1
    for (int s = 0; s < NS; s += 2) {
        cpstage(1, (s + 1) * BK);
        CP_COMMIT();
        compute(0);
        CP_WAIT0();
        __syncthreads();
        const bool more = (s + 2) < NS;
        if (more) {
            cpstage(0, (s + 2) * BK);
            CP_COMMIT();
        }
        compute(1);
        if (more) {
            CP_WAIT0();
            __syncthreads();
        }
    }

    // weighted scatter-add epilogue
#pragma unroll
    for (int mm = 0; mm < 2; mm++) {
#pragma unroll
        for (int nn = 0; nn < 4; nn++) {
            const int r = wm + mm * 16 + grp;
            const int c = n0 + wn + nn * 8 + tig * 2;
            const float* D = acc[mm][nn];
            int t1 = sm.stok[r];
            if (t1 >= 0) {
                float w = sm.sw[r];
                atomicAdd(&out[(size_t)t1 * H_ + c],     w * D[0]);
                atomicAdd(&out[(size_t)t1 * H_ + c + 1], w * D[1]);
            }
            int t2 = sm.stok[r + 8];
            if (t2 >= 0) {
                float w = sm.sw[r + 8];
                atomicAdd(&out[(size_t)t2 * H_ + c],     w * D[2]);
                atomicAdd(&out[(size_t)t2 * H_ + c + 1], w * D[3]);
            }
        }
    }
    __syncthreads();
}

__global__ __launch_bounds__(256, 2)
void moe_kernel(float* __restrict__ out) {
    __shared__ SmemPool sm;
    const int tid = threadIdx.x;
    const int nw1   = g_nw1;
    const int nwtot = g_nwtot;

    for (;;) {
        if (tid == 0) sm.item = atomicAdd(&g_next, 1);
        __syncthreads();
        const int i = sm.item;
        if (i >= nwtot) return;
        if (i < nw1) {
            const int mt = i / 22, ny = i % 22;
            g1_tile(sm, g_mt_e[mt], g_mt_m0[mt], ny, mt);
        } else {
            const int j = i - nw1;
            const int mt = j / 32, ny = j % 32;
            g2_tile(sm, out, g_mt_e[mt], g_mt_m0[mt], ny, mt);
        }
    }
}

// ---------------- launch -----------------------------------------------------
extern "C" void kernel_launch(void* const* d_in, const int* in_sizes, int n_in,
                              void* d_out, int out_size) {
    const float* hs  = (const float*)d_in[0];   // [T, H]
    const float* gw  = (const float*)d_in[1];   // [E, H]
    const float* ws  = (const float*)d_in[2];   // [E, 2I, H]
    const float* w2s = (const float*)d_in[3];   // [E, H, I]
    float* out = (float*)d_out;                 // [T, H]
    (void)in_sizes; (void)n_in; (void)out_size; // top_k fixed at 2

    conv_kernel<<<2048, 256>>>(hs, ws, w2s);
    router_kernel<<<T_, 128>>>(hs, gw, out);
    scan_kernel<<<1, 32>>>();
    scatter_kernel<<<(T_ + 255) / 256, 256>>>();
    moe_kernel<<<296, 256>>>(out);
}

// round 17
// speedup vs baseline: 2.4696x; 1.1501x over previous
#include <cuda_runtime.h>
#include <cuda_fp16.h>
#include <cstdint>

#define T_  4096
#define H_  2048
#define I_  1408
#define E_  16
#define TI_ 2816            // 2*I
#define SLOTS (T_*2)        // 8192 (token, expert) pairs
#define MAXMT 80            // max total m-tiles: 8192/128 + 16

// ---------------- scratch (device globals: no allocation allowed) -----------
__device__ int    g_topk_ids[SLOTS];
__device__ float  g_topk_w[SLOTS];
__device__ int    g_counts[E_];
__device__ int    g_offsets[E_ + 1];
__device__ int    g_cursor[E_];
__device__ int    g_sorted_tok[SLOTS];
__device__ float  g_sorted_w[SLOTS];
__device__ int    g_sorted_slot[SLOTS];    // which top-k slot (0/1)
// fp16 operand mirrors (converted every call); 16B-aligned for cp.async.cg
__device__ __align__(16) __half g_hs16[(size_t)T_ * H_];            // 16.8 MB
__device__ __align__(16) __half g_ws16[(size_t)E_ * TI_ * H_];      // 184 MB
__device__ __align__(16) __half g_w2s16[(size_t)E_ * H_ * I_];      // 92 MB
__device__ __align__(16) __half g_hbuf16[(size_t)SLOTS * I_];       // 23 MB
// split output (slot 0 / slot 1), combined at the end: no atomics needed
__device__ __align__(16) float  g_outbuf[(size_t)2 * T_ * H_];      // 64 MB
// persistent-kernel work queue state
__device__ int    g_mt_e[MAXMT];
__device__ int    g_mt_m0[MAXMT];
__device__ int    g_done[MAXMT];
__device__ int    g_next;
__device__ int    g_nw1;
__device__ int    g_nwtot;

// ---------------- helpers ---------------------------------------------------
__device__ __forceinline__ void mma_f16(float d[4], const uint32_t a[4], const uint32_t b[2]) {
    asm volatile(
        "mma.sync.aligned.m16n8k16.row.col.f32.f16.f16.f32 "
        "{%0,%1,%2,%3}, {%4,%5,%6,%7}, {%8,%9}, {%0,%1,%2,%3};\n"
        : "+f"(d[0]), "+f"(d[1]), "+f"(d[2]), "+f"(d[3])
        : "r"(a[0]), "r"(a[1]), "r"(a[2]), "r"(a[3]), "r"(b[0]), "r"(b[1]));
}

__device__ __forceinline__ void ldsm_x4(uint32_t r[4], uint32_t saddr) {
    asm volatile("ldmatrix.sync.aligned.m8n8.x4.shared.b16 {%0,%1,%2,%3}, [%4];"
                 : "=r"(r[0]), "=r"(r[1]), "=r"(r[2]), "=r"(r[3]) : "r"(saddr));
}

// 16B async copy; pred=false -> zero-fill (src not dereferenced)
__device__ __forceinline__ void cp_async16(uint32_t dst, const void* src, bool pred) {
    int sz = pred ? 16 : 0;
    asm volatile("cp.async.cg.shared.global [%0], [%1], 16, %2;"
                 :: "r"(dst), "l"(src), "r"(sz) : "memory");
}
#define CP_COMMIT() asm volatile("cp.async.commit_group;" ::: "memory")
#define CP_WAIT0()  asm volatile("cp.async.wait_group 0;" ::: "memory")

__device__ __forceinline__ float silu_f(float x) {
    return x / (1.0f + expf(-x));
}

// ---------------- kernel 0: fp32 -> fp16 operand conversion ------------------
__global__ void conv_kernel(const float* __restrict__ hs, const float* __restrict__ ws,
                            const float* __restrict__ w2s) {
    const size_t idx    = (size_t)blockIdx.x * blockDim.x + threadIdx.x;
    const size_t stride = (size_t)gridDim.x * blockDim.x;

    const size_t WSN  = (size_t)E_ * TI_ * H_ / 4;
    const size_t W2N  = (size_t)E_ * H_ * I_ / 4;
    const size_t HSN  = (size_t)T_ * H_ / 4;

    const float4* s;
    uint2* d;

    s = (const float4*)ws;  d = (uint2*)g_ws16;
    for (size_t i = idx; i < WSN; i += stride) {
        float4 v = s[i];
        __half2 h0 = __floats2half2_rn(v.x, v.y), h1 = __floats2half2_rn(v.z, v.w);
        d[i] = make_uint2(*(uint32_t*)&h0, *(uint32_t*)&h1);
    }
    s = (const float4*)w2s; d = (uint2*)g_w2s16;
    for (size_t i = idx; i < W2N; i += stride) {
        float4 v = s[i];
        __half2 h0 = __floats2half2_rn(v.x, v.y), h1 = __floats2half2_rn(v.z, v.w);
        d[i] = make_uint2(*(uint32_t*)&h0, *(uint32_t*)&h1);
    }
    s = (const float4*)hs;  d = (uint2*)g_hs16;
    for (size_t i = idx; i < HSN; i += stride) {
        float4 v = s[i];
        __half2 h0 = __floats2half2_rn(v.x, v.y), h1 = __floats2half2_rn(v.z, v.w);
        d[i] = make_uint2(*(uint32_t*)&h0, *(uint32_t*)&h1);
    }
}

// ---------------- kernel 1: router (1 block/token) ---------------------------
__global__ void router_kernel(const float* __restrict__ hs, const float* __restrict__ gw) {
    __shared__ float sh[H_];
    __shared__ float slog[E_];
    const int t = blockIdx.x;
    const int tid = threadIdx.x;

    const float* hr = hs + (size_t)t * H_;
    for (int i = tid; i < H_; i += 128) sh[i] = hr[i];
    __syncthreads();

    const int e = tid >> 3;
    const int r = tid & 7;
    const float* gr = gw + (size_t)e * H_;
    float s = 0.0f;
    for (int k = r; k < H_; k += 8) s += sh[k] * gr[k];
    s += __shfl_xor_sync(0xffffffffu, s, 4);
    s += __shfl_xor_sync(0xffffffffu, s, 2);
    s += __shfl_xor_sync(0xffffffffu, s, 1);
    if (r == 0) slog[e] = s;
    __syncthreads();

    if (tid == 0) {
        int i0 = 0; float l0 = slog[0];
        for (int i = 1; i < E_; i++) if (slog[i] > l0) { l0 = slog[i]; i0 = i; }
        int i1 = -1; float l1 = -1e30f;
        for (int i = 0; i < E_; i++) if (i != i0 && slog[i] > l1) { l1 = slog[i]; i1 = i; }
        float p1 = expf(l1 - l0);
        float inv = 1.0f / (1.0f + p1);
        g_topk_ids[2 * t]     = i0;
        g_topk_ids[2 * t + 1] = i1;
        g_topk_w[2 * t]     = inv;
        g_topk_w[2 * t + 1] = p1 * inv;
        atomicAdd(&g_counts[i0], 1);
        atomicAdd(&g_counts[i1], 1);
    }
}

// ---------------- kernel 2: scan + dense tile table + queue reset ------------
__global__ void scan_kernel() {
    if (threadIdx.x == 0) {
        int acc = 0;
        g_offsets[0] = 0;
        for (int e = 0; e < E_; e++) {
            g_cursor[e] = acc;
            acc += g_counts[e];
            g_offsets[e + 1] = acc;
        }
        int nmt = 0;
        for (int e = 0; e < E_; e++) {
            int rows = g_offsets[e + 1] - g_offsets[e];
            for (int m0 = 0; m0 < rows; m0 += 128) {
                g_mt_e[nmt]  = e;
                g_mt_m0[nmt] = m0;
                nmt++;
            }
        }
        g_nw1   = nmt * 22;             // g1: I/64 n-tiles
        g_nwtot = nmt * 22 + nmt * 16;  // + g2: H/128 n-tiles
        g_next  = 0;
        for (int i = 0; i < MAXMT; i++) g_done[i] = 0;
    }
}

// ---------------- kernel 3: scatter (records slot k) -------------------------
__global__ void scatter_kernel() {
    int t = blockIdx.x * blockDim.x + threadIdx.x;
    if (t < E_) g_counts[t] = 0;   // reset for next replay
    if (t >= T_) return;
#pragma unroll
    for (int k = 0; k < 2; k++) {
        int e = g_topk_ids[2 * t + k];
        int pos = atomicAdd(&g_cursor[e], 1);
        g_sorted_tok[pos]  = t;
        g_sorted_w[pos]    = g_topk_w[2 * t + k];
        g_sorted_slot[pos] = k;
    }
}

// ---------------- GEMM tiling constants --------------------------------------
constexpr int BM = 128;
constexpr int BK = 16;
constexpr int AST = 12;     // u32 stride per row (8 used + 4 pad) — ldmatrix conflict-free

struct SmemPool {
    uint32_t As[2][BM * AST];    // 12 KB
    uint32_t Bs[2][128 * AST];   // 12 KB (g1: gate rows 0-63, up rows 64-127; g2: 128 N rows)
    int      stok[BM];
    float    sw[BM];
    int      sslot[BM];
    int      item;
};

// ---------------- g1 tile: BM=128 x (64 gate + 64 up), K=H -------------------
__device__ __forceinline__ void g1_tile(SmemPool& sm, int e, int m0, int ny, int mt) {
    const int off  = g_offsets[e];
    const int rows = g_offsets[e + 1] - off;
    const int n0   = ny * 64;
    const int tid  = threadIdx.x;

    if (tid < BM) {
        int am = m0 + tid;
        sm.stok[tid] = (am < rows) ? g_sorted_tok[off + am] : -1;
    }
    __syncthreads();

    // A: 256 x 16B chunks (row=tid>>1, half=tid&1); B: tid<128 gate, tid>=128 up
    const int arow = tid >> 1, ahalf = tid & 1;
    const int tokA = sm.stok[arow];
    const bool aPred = (tokA >= 0);
    const __half* aSrc = g_hs16 + (size_t)(aPred ? tokA : 0) * H_ + ahalf * 8;
    const bool isBu = (tid >= 128);
    const int bi = tid & 127;
    const int brow = bi >> 1, bhalf = bi & 1;
    const __half* bSrc = g_ws16 + ((size_t)e * TI_ + (isBu ? I_ : 0) + n0 + brow) * H_ + bhalf * 8;
    const int bsrow = brow + (isBu ? 64 : 0);    // up rows live at 64-127 of Bs

    uint32_t aDst[2], bDst[2];
    aDst[0] = (uint32_t)__cvta_generic_to_shared(&sm.As[0][arow * AST + ahalf * 4]);
    aDst[1] = (uint32_t)__cvta_generic_to_shared(&sm.As[1][arow * AST + ahalf * 4]);
    bDst[0] = (uint32_t)__cvta_generic_to_shared(&sm.Bs[0][bsrow * AST + bhalf * 4]);
    bDst[1] = (uint32_t)__cvta_generic_to_shared(&sm.Bs[1][bsrow * AST + bhalf * 4]);

    float accG[2][4][4] = {};
    float accU[2][4][4] = {};

    const int lane = tid & 31, warp = tid >> 5;
    const int wm = (warp >> 1) * 32;
    const int wn = (warp & 1) * 32;
    const int grp = lane >> 2, tig = lane & 3;

    uint32_t sA[2], sB[2];
    sA[0] = (uint32_t)__cvta_generic_to_shared(&sm.As[0][0]);
    sA[1] = (uint32_t)__cvta_generic_to_shared(&sm.As[1][0]);
    sB[0] = (uint32_t)__cvta_generic_to_shared(&sm.Bs[0][0]);
    sB[1] = (uint32_t)__cvta_generic_to_shared(&sm.Bs[1][0]);
    const uint32_t aOff = (uint32_t)((wm + (lane & 15)) * AST * 4 + (lane >> 4) * 16);
    const uint32_t bOff = (uint32_t)((wn + ((lane >> 4) & 1) * 8 + (lane & 7)) * AST * 4
                                     + ((lane >> 3) & 1) * 16);
    const uint32_t uOff = bOff + 64 * AST * 4;   // up half of Bs

    auto cpstage = [&](int b, int k0) {
        cp_async16(aDst[b], aSrc + k0, aPred);
        cp_async16(bDst[b], bSrc + k0, true);
    };
    auto compute = [&](int b) {
        uint32_t af[2][4], gf[2][4], uf[2][4];
#pragma unroll
        for (int mm = 0; mm < 2; mm++)
            ldsm_x4(af[mm], sA[b] + aOff + (uint32_t)(mm * 16 * AST * 4));
#pragma unroll
        for (int p = 0; p < 2; p++) {
            ldsm_x4(gf[p], sB[b] + bOff + (uint32_t)(p * 16 * AST * 4));
            ldsm_x4(uf[p], sB[b] + uOff + (uint32_t)(p * 16 * AST * 4));
        }
#pragma unroll
        for (int nn = 0; nn < 4; nn++) {
            uint32_t bg2[2] = { gf[nn >> 1][(nn & 1) * 2], gf[nn >> 1][(nn & 1) * 2 + 1] };
            uint32_t bu2[2] = { uf[nn >> 1][(nn & 1) * 2], uf[nn >> 1][(nn & 1) * 2 + 1] };
#pragma unroll
            for (int mm = 0; mm < 2; mm++) {
                mma_f16(accG[mm][nn], af[mm], bg2);
                mma_f16(accU[mm][nn], af[mm], bu2);
            }
        }
    };

    cpstage(0, 0);
    CP_COMMIT();
    CP_WAIT0();
    __syncthreads();

    constexpr int NS = H_ / BK;   // 128 (even)
#pragma unroll 1
    for (int s = 0; s < NS; s += 2) {
        cpstage(1, (s + 1) * BK);
        CP_COMMIT();
        compute(0);
        CP_WAIT0();
        __syncthreads();
        const bool more = (s + 2) < NS;
        if (more) {
            cpstage(0, (s + 2) * BK);
            CP_COMMIT();
        }
        compute(1);
        if (more) {
            CP_WAIT0();
            __syncthreads();
        }
    }

    // fused SwiGLU epilogue -> hbuf16
#pragma unroll
    for (int mm = 0; mm < 2; mm++) {
#pragma unroll
        for (int nn = 0; nn < 4; nn++) {
            const int r = wm + mm * 16 + grp;
            const int c = n0 + wn + nn * 8 + tig * 2;
            const float* G = accG[mm][nn];
            const float* U = accU[mm][nn];
            if (m0 + r < rows) {
                size_t b = (size_t)(off + m0 + r) * I_ + c;
                *(__half2*)(g_hbuf16 + b) =
                    __floats2half2_rn(silu_f(G[0]) * U[0], silu_f(G[1]) * U[1]);
            }
            if (m0 + r + 8 < rows) {
                size_t b = (size_t)(off + m0 + r + 8) * I_ + c;
                *(__half2*)(g_hbuf16 + b) =
                    __floats2half2_rn(silu_f(G[2]) * U[2], silu_f(G[3]) * U[3]);
            }
        }
    }

    __syncthreads();
    __threadfence();
    if (tid == 0) atomicAdd(&g_done[mt], 1);
}

// ---------------- g2 tile: BM=128 x BN=128, K=I; non-atomic split output -----
__device__ __forceinline__ void g2_tile(SmemPool& sm, int e, int m0, int ny, int mt) {
    const int tid = threadIdx.x;

    if (tid == 0) {
        while (atomicAdd(&g_done[mt], 0) < 22) __nanosleep(200);
    }
    __syncthreads();
    __threadfence();

    const int off  = g_offsets[e];
    const int rows = g_offsets[e + 1] - off;
    const int n0   = ny * 128;

    if (tid < BM) {
        int am = m0 + tid;
        bool v = (am < rows);
        sm.stok[tid]  = v ? g_sorted_tok[off + am]  : -1;
        sm.sw[tid]    = v ? g_sorted_w[off + am]    : 0.0f;
        sm.sslot[tid] = v ? g_sorted_slot[off + am] : 0;
    }
    __syncthreads();

    const int arow = tid >> 1, ahalf = tid & 1;
    const bool aPred = (m0 + arow) < rows;
    const __half* aSrc = g_hbuf16 + (size_t)(off + (aPred ? m0 + arow : 0)) * I_ + ahalf * 8;
    const int brow = tid >> 1, bhalf = tid & 1;   // 128 B-rows, 2 chunks each
    const __half* bSrc = g_w2s16 + ((size_t)e * H_ + n0 + brow) * I_ + bhalf * 8;

    uint32_t aDst[2], bDst[2];
    aDst[0] = (uint32_t)__cvta_generic_to_shared(&sm.As[0][arow * AST + ahalf * 4]);
    aDst[1] = (uint32_t)__cvta_generic_to_shared(&sm.As[1][arow * AST + ahalf * 4]);
    bDst[0] = (uint32_t)__cvta_generic_to_shared(&sm.Bs[0][brow * AST + bhalf * 4]);
    bDst[1] = (uint32_t)__cvta_generic_to_shared(&sm.Bs[1][brow * AST + bhalf * 4]);

    float acc[2][8][4] = {};   // warp tile 32(M) x 64(N)

    const int lane = tid & 31, warp = tid >> 5;
    const int wm = (warp >> 1) * 32;
    const int wn = (warp & 1) * 64;
    const int grp = lane >> 2, tig = lane & 3;

    uint32_t sA[2], sB[2];
    sA[0] = (uint32_t)__cvta_generic_to_shared(&sm.As[0][0]);
    sA[1] = (uint32_t)__cvta_generic_to_shared(&sm.As[1][0]);
    sB[0] = (uint32_t)__cvta_generic_to_shared(&sm.Bs[0][0]);
    sB[1] = (uint32_t)__cvta_generic_to_shared(&sm.Bs[1][0]);
    const uint32_t aOff = (uint32_t)((wm + (lane & 15)) * AST * 4 + (lane >> 4) * 16);
    const uint32_t bOff = (uint32_t)((wn + ((lane >> 4) & 1) * 8 + (lane & 7)) * AST * 4
                                     + ((lane >> 3) & 1) * 16);

    auto cpstage = [&](int b, int k0) {
        cp_async16(aDst[b], aSrc + k0, aPred);
        cp_async16(bDst[b], bSrc + k0, true);
    };
    auto compute = [&](int b) {
        uint32_t af[2][4], bf[4][4];
#pragma unroll
        for (int mm = 0; mm < 2; mm++)
            ldsm_x4(af[mm], sA[b] + aOff + (uint32_t)(mm * 16 * AST * 4));
#pragma unroll
        for (int p = 0; p < 4; p++)
            ldsm_x4(bf[p], sB[b] + bOff + (uint32_t)(p * 16 * AST * 4));
#pragma unroll
        for (int nn = 0; nn < 8; nn++) {
            uint32_t b2[2] = { bf[nn >> 1][(nn & 1) * 2], bf[nn >> 1][(nn & 1) * 2 + 1] };
#pragma unroll
            for (int mm = 0; mm < 2; mm++) {
                mma_f16(acc[mm][nn], af[mm], b2);
            }
        }
    };

    cpstage(0, 0);
    CP_COMMIT();
    CP_WAIT0();
    __syncthreads();

    constexpr int NS = I_ / BK;   // 88 (even)
#pragma unroll 1
    for (int s = 0; s < NS; s += 2) {
        cpstage(1, (s + 1) * BK);
        CP_COMMIT();
        compute(0);
        CP_WAIT0();
        __syncthreads();
        const bool more = (s + 2) < NS;
        if (more) {
            cpstage(0, (s + 2) * BK);
            CP_COMMIT();
        }
        compute(1);
        if (more) {
            CP_WAIT0();
            __syncthreads();
        }
    }

    // non-atomic weighted epilogue into split buffer: (t, slot, c) unique
#pragma unroll
    for (int mm = 0; mm < 2; mm++) {
#pragma unroll
        for (int nn = 0; nn < 8; nn++) {
            const int r = wm + mm * 16 + grp;
            const int c = n0 + wn + nn * 8 + tig * 2;
            const float* D = acc[mm][nn];
            int t1 = sm.stok[r];
            if (t1 >= 0) {
                float w = sm.sw[r];
                float2 v = make_float2(w * D[0], w * D[1]);
                *(float2*)&g_outbuf[((size_t)sm.sslot[r] * T_ + t1) * H_ + c] = v;
            }
            int t2 = sm.stok[r + 8];
            if (t2 >= 0) {
                float w = sm.sw[r + 8];
                float2 v = make_float2(w * D[2], w * D[3]);
                *(float2*)&g_outbuf[((size_t)sm.sslot[r + 8] * T_ + t2) * H_ + c] = v;
            }
        }
    }
    __syncthreads();
}

__global__ __launch_bounds__(256, 2)
void moe_kernel() {
    __shared__ SmemPool sm;
    const int tid = threadIdx.x;
    const int nw1   = g_nw1;
    const int nwtot = g_nwtot;

    for (;;) {
        if (tid == 0) sm.item = atomicAdd(&g_next, 1);
        __syncthreads();
        const int i = sm.item;
        if (i >= nwtot) return;
        if (i < nw1) {
            const int mt = i / 22, ny = i % 22;
            g1_tile(sm, g_mt_e[mt], g_mt_m0[mt], ny, mt);
        } else {
            const int j = i - nw1;
            const int mt = j / 16, ny = j % 16;
            g2_tile(sm, g_mt_e[mt], g_mt_m0[mt], ny, mt);
        }
    }
}

// ---------------- kernel 5: combine split buffers -> out ---------------------
__global__ void combine_kernel(float* __restrict__ out) {
    const size_t i = (size_t)blockIdx.x * blockDim.x + threadIdx.x;
    const size_t n = (size_t)T_ * H_ / 4;
    if (i >= n) return;
    const float4 a = ((const float4*)g_outbuf)[i];
    const float4 b = ((const float4*)(g_outbuf + (size_t)T_ * H_))[i];
    ((float4*)out)[i] = make_float4(a.x + b.x, a.y + b.y, a.z + b.z, a.w + b.w);
}

// ---------------- launch -----------------------------------------------------
extern "C" void kernel_launch(void* const* d_in, const int* in_sizes, int n_in,
                              void* d_out, int out_size) {
    const float* hs  = (const float*)d_in[0];   // [T, H]
    const float* gw  = (const float*)d_in[1];   // [E, H]
    const float* ws  = (const float*)d_in[2];   // [E, 2I, H]
    const float* w2s = (const float*)d_in[3];   // [E, H, I]
    float* out = (float*)d_out;                 // [T, H]
    (void)in_sizes; (void)n_in; (void)out_size; // top_k fixed at 2

    conv_kernel<<<2048, 256>>>(hs, ws, w2s);
    router_kernel<<<T_, 128>>>(hs, gw);
    scan_kernel<<<1, 32>>>();
    scatter_kernel<<<(T_ + 255) / 256, 256>>>();
    moe_kernel<<<296, 256>>>();
    combine_kernel<<<(T_ * H_ / 4 + 255) / 256, 256>>>(out);
}